// round 1
// baseline (speedup 1.0000x reference)
#include <cuda_runtime.h>

#define DI __device__ __forceinline__

// fake_quant_act: clip(round(x/s), -128, 127) * s, round-half-to-even, exact fp32 div.
DI float fq(float x, float s) {
    float q = rintf(__fdiv_rn(x, s));
    q = fminf(fmaxf(q, -128.0f), 127.0f);
    return q * s;
}

// ---------------- device global scratch (no allocations allowed) ----------------
__device__ float g_bufA[(size_t)32 * 32 * 254 * 254];   // 264 MB ping
__device__ float g_bufB[(size_t)32 * 32 * 254 * 254];   // 264 MB pong
__device__ float g_qw1[1 * 3 * 3 * 16];
__device__ float g_qw2[16 * 3 * 3 * 32];
__device__ float g_qw3[32 * 5 * 5 * 32];
__device__ float g_qw4[32 * 3 * 3 * 16];
__device__ float g_qwc[16 * 10];
__device__ float g_feat[32 * 16];

// ---------------- weight fake-quant + transpose to [ic][ky][kx][oc] ----------------
template <int IC, int OC, int K>
__global__ void wquant_kernel(const float* __restrict__ w, float* __restrict__ dst) {
    __shared__ float red[256];
    const int n = OC * IC * K * K;
    float m = 0.0f;
    for (int i = threadIdx.x; i < n; i += 256) m = fmaxf(m, fabsf(w[i]));
    red[threadIdx.x] = m;
    __syncthreads();
    for (int s = 128; s > 0; s >>= 1) {
        if (threadIdx.x < s) red[threadIdx.x] = fmaxf(red[threadIdx.x], red[threadIdx.x + s]);
        __syncthreads();
    }
    const float scale = __fdiv_rn(red[0], 127.0f);
    for (int i = threadIdx.x; i < n; i += 256) {
        int kx = i % K;
        int ky = (i / K) % K;
        int ic = (i / (K * K)) % IC;
        int oc = i / (K * K * IC);
        float q = rintf(__fdiv_rn(w[i], scale));
        q = fminf(fmaxf(q, -128.0f), 127.0f);
        dst[((ic * K + ky) * K + kx) * OC + oc] = q * scale;
    }
}

// ---------------- direct conv, register-blocked PX pixels x OCR channels ----------------
// block: 32 x-lanes (PX px each) * (OC/OCR) oc-groups. Full weight tensor in smem.
// epilogue: +bias, relu, fq(sa), fq(sb).
template <int IC, int OC, int K, int PAD, int PX, int OCR, bool IN_FQ>
__global__ void conv_kernel(const float* __restrict__ in, const float* __restrict__ wq,
                            const float* __restrict__ bias, float* __restrict__ out,
                            int H_in, int W_in, int H_out, int W_out,
                            const float* __restrict__ scales,
                            int s_in_idx, int s_a_idx, int s_b_idx) {
    extern __shared__ float wsm[];
    constexpr int LANES = 32;
    constexpr int OCG = OC / OCR;
    constexpr int NT = LANES * OCG;
    constexpr int VW = PX + K - 1;

    const int tid  = threadIdx.x;
    const int lane = tid % LANES;
    const int ocg  = tid / LANES;
    const int oc0  = ocg * OCR;
    const int x0   = blockIdx.x * (LANES * PX) + lane * PX;
    const int y    = blockIdx.y;
    const int b    = blockIdx.z;

    for (int i = tid; i < IC * K * K * OC; i += NT) wsm[i] = wq[i];
    __syncthreads();

    const float s_in = IN_FQ ? scales[s_in_idx] : 1.0f;

    float acc[PX][OCR];
#pragma unroll
    for (int p = 0; p < PX; p++)
#pragma unroll
        for (int j = 0; j < OCR; j++) acc[p][j] = 0.0f;

    for (int ic = 0; ic < IC; ic++) {
        const float* base = in + (size_t)(b * IC + ic) * H_in * W_in;
#pragma unroll
        for (int ky = 0; ky < K; ky++) {
            int iy = y + ky - PAD;
            if (iy < 0 || iy >= H_in) continue;
            const float* row = base + (size_t)iy * W_in;
            float v[VW];
#pragma unroll
            for (int u = 0; u < VW; u++) {
                int ix = x0 + u - PAD;
                float val = (ix >= 0 && ix < W_in) ? row[ix] : 0.0f;
                if (IN_FQ) val = fq(val, s_in);
                v[u] = val;
            }
            const float* wrow = wsm + ((ic * K + ky) * K) * OC + oc0;
#pragma unroll
            for (int kx = 0; kx < K; kx++) {
                float w[OCR];
#pragma unroll
                for (int j = 0; j < OCR; j++) w[j] = wrow[kx * OC + j];
#pragma unroll
                for (int p = 0; p < PX; p++)
#pragma unroll
                    for (int j = 0; j < OCR; j++)
                        acc[p][j] = fmaf(v[kx + p], w[j], acc[p][j]);
            }
        }
    }

    const float sa = scales[s_a_idx];
    const float sb = scales[s_b_idx];
#pragma unroll
    for (int j = 0; j < OCR; j++) {
        const float bv = bias[oc0 + j];
#pragma unroll
        for (int p = 0; p < PX; p++) {
            int x = x0 + p;
            if (x < W_out) {
                float r = acc[p][j] + bv;
                r = fmaxf(r, 0.0f);     // relu
                r = fq(r, sa);          // reluN quant
                r = fq(r, sb);          // quantN
                out[((size_t)(b * OC + oc0 + j) * H_out + y) * W_out + x] = r;
            }
        }
    }
}

// ---------------- maxpool 2x2 + fq(s7) ----------------
__global__ void pool_kernel(const float* __restrict__ in, float* __restrict__ out,
                            const float* __restrict__ scales) {
    int idx = blockIdx.x * blockDim.x + threadIdx.x;
    const int total = 32 * 32 * 127 * 127;
    if (idx >= total) return;
    int x  = idx % 127;
    int y  = (idx / 127) % 127;
    int bc = idx / (127 * 127);
    const float* p = in + ((size_t)bc * 254 + 2 * y) * 254 + 2 * x;
    float m = fmaxf(fmaxf(p[0], p[1]), fmaxf(p[254], p[255]));
    out[idx] = fq(m, scales[7]);
}

// ---------------- global average pool + fq(s10) ----------------
__global__ void gap_kernel(const float* __restrict__ in, const float* __restrict__ scales) {
    __shared__ float red[256];
    const int bc = blockIdx.x;                 // b*16 + c, 512 blocks
    const float* p = in + (size_t)bc * (125 * 125);
    float s = 0.0f;
    for (int i = threadIdx.x; i < 125 * 125; i += 256) s += p[i];
    red[threadIdx.x] = s;
    __syncthreads();
    for (int t = 128; t > 0; t >>= 1) {
        if (threadIdx.x < t) red[threadIdx.x] += red[threadIdx.x + t];
        __syncthreads();
    }
    if (threadIdx.x == 0) {
        float mean = __fdiv_rn(red[0], 15625.0f);
        g_feat[bc] = fq(mean, scales[10]);
    }
}

// ---------------- classifier: feat[32,16] @ qwc^T[16,10] + bc ----------------
__global__ void fc_kernel(const float* __restrict__ bias, float* __restrict__ out) {
    int t = threadIdx.x;
    if (t >= 320) return;
    int b = t / 10, j = t % 10;
    float s = bias[j];
#pragma unroll
    for (int k = 0; k < 16; k++) s += g_feat[b * 16 + k] * g_qwc[k * 10 + j];
    out[b * 10 + j] = s;
}

// ---------------- launcher ----------------
extern "C" void kernel_launch(void* const* d_in, const int* in_sizes, int n_in,
                              void* d_out, int out_size) {
    const float* x   = (const float*)d_in[0];
    const float* w1  = (const float*)d_in[1];
    const float* b1  = (const float*)d_in[2];
    const float* w2  = (const float*)d_in[3];
    const float* b2  = (const float*)d_in[4];
    const float* w3  = (const float*)d_in[5];
    const float* b3  = (const float*)d_in[6];
    const float* w4  = (const float*)d_in[7];
    const float* b4  = (const float*)d_in[8];
    const float* wc  = (const float*)d_in[9];
    const float* bc  = (const float*)d_in[10];
    const float* sc  = (const float*)d_in[11];
    float* out = (float*)d_out;

    float *bufA, *bufB, *qw1, *qw2, *qw3, *qw4, *qwc;
    cudaGetSymbolAddress((void**)&bufA, g_bufA);
    cudaGetSymbolAddress((void**)&bufB, g_bufB);
    cudaGetSymbolAddress((void**)&qw1, g_qw1);
    cudaGetSymbolAddress((void**)&qw2, g_qw2);
    cudaGetSymbolAddress((void**)&qw3, g_qw3);
    cudaGetSymbolAddress((void**)&qw4, g_qw4);
    cudaGetSymbolAddress((void**)&qwc, g_qwc);

    // conv3 weight smem: 32*25*32*4 = 100 KB > 48 KB default
    cudaFuncSetAttribute(conv_kernel<32, 32, 5, 2, 4, 8, false>,
                         cudaFuncAttributeMaxDynamicSharedMemorySize, 32 * 25 * 32 * 4);

    // weight fake-quant (tiny)
    wquant_kernel<1, 16, 3><<<1, 256>>>(w1, qw1);
    wquant_kernel<16, 32, 3><<<1, 256>>>(w2, qw2);
    wquant_kernel<32, 32, 5><<<1, 256>>>(w3, qw3);
    wquant_kernel<32, 16, 3><<<1, 256>>>(w4, qw4);
    wquant_kernel<16, 10, 1><<<1, 256>>>(wc, qwc);

    // conv1: 1->16, 3x3 valid, input fq(s0) on the fly, epi fq(s1),fq(s2)
    conv_kernel<1, 16, 3, 0, 4, 4, true><<<dim3(2, 254, 32), 128, 1 * 9 * 16 * 4>>>(
        x, qw1, b1, bufA, 256, 256, 254, 254, sc, 0, 1, 2);

    // conv2: 16->32, 3x3 same, epi fq(s3),fq(s4)
    conv_kernel<16, 32, 3, 1, 4, 8, false><<<dim3(2, 254, 32), 128, 16 * 9 * 32 * 4>>>(
        bufA, qw2, b2, bufB, 254, 254, 254, 254, sc, 0, 3, 4);

    // conv3: 32->32, 5x5 same, epi fq(s5),fq(s6)
    conv_kernel<32, 32, 5, 2, 4, 8, false><<<dim3(2, 254, 32), 128, 32 * 25 * 32 * 4>>>(
        bufB, qw3, b3, bufA, 254, 254, 254, 254, sc, 0, 5, 6);

    // maxpool 2x2 + fq(s7)
    pool_kernel<<<(32 * 32 * 127 * 127 + 255) / 256, 256>>>(bufA, bufB, sc);

    // conv4: 32->16, 3x3 valid, epi fq(s8),fq(s9)
    conv_kernel<32, 16, 3, 0, 4, 4, false><<<dim3(1, 125, 32), 128, 32 * 9 * 16 * 4>>>(
        bufB, qw4, b4, bufA, 127, 127, 125, 125, sc, 0, 8, 9);

    // global avg pool + fq(s10)
    gap_kernel<<<512, 256>>>(bufA, sc);

    // classifier
    fc_kernel<<<1, 512>>>(bc, out);
}

// round 4
// speedup vs baseline: 4.3239x; 4.3239x over previous
#include <cuda_runtime.h>

#define DI __device__ __forceinline__

// exact fake-quant: clip(round-half-even(x/s), -128, 127)
DI float fq_q(float x, float s) {
    float q = rintf(__fdiv_rn(x, s));
    return fminf(fmaxf(q, -128.0f), 127.0f);
}
DI float fq(float x, float s) { return fq_q(x, s) * s; }

DI int get_byte(int w, int k) { return (int)((signed char)(w >> (8 * k))); }

// ---------------- device global scratch ----------------
__device__ int         g_bufA[(size_t)32 * 8 * 254 * 254];   // 66 MB packed int8x4
__device__ int         g_bufB[(size_t)32 * 8 * 254 * 254];   // 66 MB
__device__ signed char g_in0[(size_t)32 * 256 * 256];
__device__ int   g_qw1[9 * 16];          // [ky][kx][oc] int q
__device__ int   g_qw2[4 * 9 * 32];      // packed [icg][ky][kx][oc]
__device__ int   g_qw3[8 * 25 * 32];
__device__ int   g_qw4[8 * 9 * 16];
__device__ float g_qwc[16 * 10];
__device__ float g_wscale[5];            // per-layer weight scales
__device__ float g_feat[32 * 16];

// ---------------- input quant: fp32 -> int8 codes ----------------
__global__ void inquant_kernel(const float* __restrict__ x, signed char* __restrict__ out,
                               const float* __restrict__ scales) {
    int i = blockIdx.x * 256 + threadIdx.x;
    if (i < 32 * 256 * 256) {
        out[i] = (signed char)(int)fq_q(x[i], scales[0]);
    }
}

// ---------------- conv1 weight quant (IC=1) -> int q [ky][kx][oc] ----------------
__global__ void wquant_c1(const float* __restrict__ w, int* __restrict__ dst,
                          float* __restrict__ scale_out) {
    __shared__ float red[256];
    const int n = 16 * 9;
    float m = 0.0f;
    for (int i = threadIdx.x; i < n; i += 256) m = fmaxf(m, fabsf(w[i]));
    red[threadIdx.x] = m;
    __syncthreads();
    for (int s = 128; s > 0; s >>= 1) {
        if (threadIdx.x < s) red[threadIdx.x] = fmaxf(red[threadIdx.x], red[threadIdx.x + s]);
        __syncthreads();
    }
    const float scale = __fdiv_rn(red[0], 127.0f);
    if (threadIdx.x == 0) *scale_out = scale;
    for (int i = threadIdx.x; i < n; i += 256) {
        int kx = i % 3, ky = (i / 3) % 3, oc = i / 9;
        dst[(ky * 3 + kx) * 16 + oc] = (int)fq_q(w[i], scale);
    }
}

// ---------------- packed weight quant: [oc][ic][ky][kx] -> int32 [icg][ky][kx][oc] ----------------
template <int IC, int OC, int K>
__global__ void wquant_pack(const float* __restrict__ w, int* __restrict__ dst,
                            float* __restrict__ scale_out) {
    __shared__ float red[256];
    const int n = OC * IC * K * K;
    float m = 0.0f;
    for (int i = threadIdx.x; i < n; i += 256) m = fmaxf(m, fabsf(w[i]));
    red[threadIdx.x] = m;
    __syncthreads();
    for (int s = 128; s > 0; s >>= 1) {
        if (threadIdx.x < s) red[threadIdx.x] = fmaxf(red[threadIdx.x], red[threadIdx.x + s]);
        __syncthreads();
    }
    const float scale = __fdiv_rn(red[0], 127.0f);
    if (threadIdx.x == 0) *scale_out = scale;
    const int nw = (IC / 4) * K * K * OC;
    for (int i = threadIdx.x; i < nw; i += 256) {
        int oc  = i % OC;
        int kx  = (i / OC) % K;
        int ky  = (i / (OC * K)) % K;
        int icg = i / (OC * K * K);
        int word = 0;
#pragma unroll
        for (int k = 0; k < 4; k++) {
            int ic = icg * 4 + k;
            int qi = (int)fq_q(w[((oc * IC + ic) * K + ky) * K + kx], scale);
            word |= (qi & 0xFF) << (8 * k);
        }
        dst[((icg * K + ky) * K + kx) * OC + oc] = word;
    }
}

// quant epilogue -> next layer int8 code
DI int epi_q(int acc, float cs, float bv, float sa, float sb) {
    float r = fmaf((float)acc, cs, bv);
    r = fmaxf(r, 0.0f);                     // relu
    float v1 = fq(r, sa);                   // fq(sa)
    return (int)fq_q(v1, sb);               // fq(sb), keep code
}

// ---------------- conv1: IC=1 int8 input, int MAC ----------------
__global__ void __launch_bounds__(128) conv1_kernel(
    const signed char* __restrict__ in, const int* __restrict__ wq,
    const float* __restrict__ bias, int* __restrict__ out,
    const float* __restrict__ scales, const float* __restrict__ wscale) {
    __shared__ int wsm[144];
    const int tid = threadIdx.x;
    const int lane = tid % 32, ocg = tid / 32;
    for (int i = tid; i < 144; i += 128) wsm[i] = wq[i];   // FIX: strided, covers all 144
    __syncthreads();
    const int x0 = blockIdx.x * 128 + lane * 4;
    const int y = blockIdx.y, b = blockIdx.z;
    const int oc0 = ocg * 4;

    int acc[4][4];
#pragma unroll
    for (int p = 0; p < 4; p++)
#pragma unroll
        for (int j = 0; j < 4; j++) acc[p][j] = 0;

    const signed char* base = in + (size_t)b * 256 * 256;
#pragma unroll
    for (int ky = 0; ky < 3; ky++) {
        const signed char* row = base + (size_t)(y + ky) * 256;
        int v[6];
#pragma unroll
        for (int u = 0; u < 6; u++) {
            int ix = x0 + u;
            v[u] = (ix < 256) ? (int)row[ix] : 0;
        }
#pragma unroll
        for (int kx = 0; kx < 3; kx++) {
            int w[4];
#pragma unroll
            for (int j = 0; j < 4; j++) w[j] = wsm[(ky * 3 + kx) * 16 + oc0 + j];
#pragma unroll
            for (int p = 0; p < 4; p++)
#pragma unroll
                for (int j = 0; j < 4; j++) acc[p][j] += v[kx + p] * w[j];
        }
    }

    const float cs = scales[0] * wscale[0];
    const float sa = scales[1], sb = scales[2];
    float bv[4];
#pragma unroll
    for (int j = 0; j < 4; j++) bv[j] = bias[oc0 + j];
#pragma unroll
    for (int p = 0; p < 4; p++) {
        int x = x0 + p;
        if (x < 254) {
            int word = 0;
#pragma unroll
            for (int j = 0; j < 4; j++)
                word |= (epi_q(acc[p][j], cs, bv[j], sa, sb) & 0xFF) << (8 * j);
            out[((size_t)(b * 4 + ocg) * 254 + y) * 254 + x] = word;
        }
    }
}

// ---------------- generic dp4a conv ----------------
// block: 32 lanes (PX px each) x (OC/OCR) oc-groups. packed weights in smem.
template <int ICG, int OC, int K, int PAD, int PX, int OCR>
__global__ void __launch_bounds__(32 * OC / OCR) conv_q_kernel(
    const int* __restrict__ in, const int* __restrict__ wq,
    const float* __restrict__ bias, int* __restrict__ out,
    int H, int W, int Ho, int Wo,
    const float* __restrict__ scales, const float* __restrict__ wscale,
    int s_in, int s_a, int s_b) {
    extern __shared__ int wsm[];
    constexpr int OCG = OC / OCR;
    constexpr int NT = 32 * OCG;
    constexpr int VW = PX + K - 1;
    constexpr int NW = ICG * K * K * OC;

    const int tid = threadIdx.x;
    const int lane = tid % 32, ocg = tid / 32;
    const int oc0 = ocg * OCR;
    const int x0 = blockIdx.x * (32 * PX) + lane * PX;
    const int y = blockIdx.y, b = blockIdx.z;

    for (int i = tid; i < NW; i += NT) wsm[i] = wq[i];
    __syncthreads();

    int acc[PX][OCR];
#pragma unroll
    for (int p = 0; p < PX; p++)
#pragma unroll
        for (int j = 0; j < OCR; j++) acc[p][j] = 0;

#pragma unroll
    for (int icg = 0; icg < ICG; icg++) {
        const int* base = in + (size_t)(b * ICG + icg) * H * W;
#pragma unroll
        for (int ky = 0; ky < K; ky++) {
            int iy = y + ky - PAD;
            if (iy < 0 || iy >= H) continue;
            const int* row = base + (size_t)iy * W;
            int v[VW];
#pragma unroll
            for (int u = 0; u < VW; u++) {
                int ix = x0 + u - PAD;
                v[u] = (ix >= 0 && ix < W) ? row[ix] : 0;
            }
            const int* wrow = wsm + ((icg * K + ky) * K) * OC + oc0;
#pragma unroll
            for (int kx = 0; kx < K; kx++) {
                int w[OCR];
#pragma unroll
                for (int j = 0; j < OCR; j++) w[j] = wrow[kx * OC + j];
#pragma unroll
                for (int p = 0; p < PX; p++)
#pragma unroll
                    for (int j = 0; j < OCR; j++)
                        acc[p][j] = __dp4a(v[kx + p], w[j], acc[p][j]);
            }
        }
    }

    const float cs = scales[s_in] * wscale[0];
    const float sa = scales[s_a], sb = scales[s_b];
    float bv[OCR];
#pragma unroll
    for (int j = 0; j < OCR; j++) bv[j] = bias[oc0 + j];

#pragma unroll
    for (int p = 0; p < PX; p++) {
        int x = x0 + p;
        if (x < Wo) {
#pragma unroll
            for (int g = 0; g < OCR / 4; g++) {
                int word = 0;
#pragma unroll
                for (int k = 0; k < 4; k++)
                    word |= (epi_q(acc[p][g * 4 + k], cs, bv[g * 4 + k], sa, sb) & 0xFF)
                            << (8 * k);
                out[((size_t)(b * (OC / 4) + oc0 / 4 + g) * Ho + y) * Wo + x] = word;
            }
        }
    }
}

// ---------------- maxpool 2x2 bytewise + requant s6 -> s7 ----------------
__global__ void pool_q_kernel(const int* __restrict__ in, int* __restrict__ out,
                              const float* __restrict__ scales) {
    int idx = blockIdx.x * 256 + threadIdx.x;
    const int total = 32 * 8 * 127 * 127;
    if (idx >= total) return;
    int x = idx % 127;
    int y = (idx / 127) % 127;
    int bcg = idx / (127 * 127);
    const int* p = in + ((size_t)bcg * 254 + 2 * y) * 254 + 2 * x;
    int m = __vmaxs4(__vmaxs4(p[0], p[1]), __vmaxs4(p[254], p[255]));
    const float s6 = scales[6], s7 = scales[7];
    int word = 0;
#pragma unroll
    for (int k = 0; k < 4; k++) {
        float v = (float)get_byte(m, k) * s6;
        word |= ((int)fq_q(v, s7) & 0xFF) << (8 * k);
    }
    out[idx] = word;
}

// ---------------- global avg pool (int sums) + fq(s10) ----------------
__global__ void gap_q_kernel(const int* __restrict__ in, const float* __restrict__ scales) {
    __shared__ int4 red[256];
    const int bcg = blockIdx.x;                  // b*4 + cg
    const int* p = in + (size_t)bcg * (125 * 125);
    int s0 = 0, s1 = 0, s2 = 0, s3 = 0;
    for (int i = threadIdx.x; i < 125 * 125; i += 256) {
        int w = p[i];
        s0 += get_byte(w, 0); s1 += get_byte(w, 1);
        s2 += get_byte(w, 2); s3 += get_byte(w, 3);
    }
    red[threadIdx.x] = make_int4(s0, s1, s2, s3);
    __syncthreads();
    for (int t = 128; t > 0; t >>= 1) {
        if (threadIdx.x < t) {
            int4 a = red[threadIdx.x], c = red[threadIdx.x + t];
            red[threadIdx.x] = make_int4(a.x + c.x, a.y + c.y, a.z + c.z, a.w + c.w);
        }
        __syncthreads();
    }
    if (threadIdx.x == 0) {
        const float s9 = scales[9], s10 = scales[10];
        int b = bcg / 4, cg = bcg % 4;
        int sums[4] = {red[0].x, red[0].y, red[0].z, red[0].w};
#pragma unroll
        for (int k = 0; k < 4; k++) {
            float mean = __fdiv_rn((float)sums[k] * s9, 15625.0f);
            g_feat[b * 16 + cg * 4 + k] = fq(mean, s10);
        }
    }
}

// ---------------- fc weight quant (float, transposed [ic][oc]) ----------------
__global__ void wquant_fc(const float* __restrict__ w, float* __restrict__ dst) {
    __shared__ float red[256];
    const int n = 160;
    float m = 0.0f;
    for (int i = threadIdx.x; i < n; i += 256) m = fmaxf(m, fabsf(w[i]));
    red[threadIdx.x] = m;
    __syncthreads();
    for (int s = 128; s > 0; s >>= 1) {
        if (threadIdx.x < s) red[threadIdx.x] = fmaxf(red[threadIdx.x], red[threadIdx.x + s]);
        __syncthreads();
    }
    const float scale = __fdiv_rn(red[0], 127.0f);
    for (int i = threadIdx.x; i < n; i += 256) {
        int ic = i % 16, oc = i / 16;
        dst[ic * 10 + oc] = fq_q(w[i], scale) * scale;
    }
}

// ---------------- classifier ----------------
__global__ void fc_kernel(const float* __restrict__ bias, float* __restrict__ out) {
    int t = threadIdx.x;
    if (t >= 320) return;
    int b = t / 10, j = t % 10;
    float s = bias[j];
#pragma unroll
    for (int k = 0; k < 16; k++) s += g_feat[b * 16 + k] * g_qwc[k * 10 + j];
    out[b * 10 + j] = s;
}

// ---------------- launcher ----------------
extern "C" void kernel_launch(void* const* d_in, const int* in_sizes, int n_in,
                              void* d_out, int out_size) {
    const float* x  = (const float*)d_in[0];
    const float* w1 = (const float*)d_in[1];
    const float* b1 = (const float*)d_in[2];
    const float* w2 = (const float*)d_in[3];
    const float* b2 = (const float*)d_in[4];
    const float* w3 = (const float*)d_in[5];
    const float* b3 = (const float*)d_in[6];
    const float* w4 = (const float*)d_in[7];
    const float* b4 = (const float*)d_in[8];
    const float* wc = (const float*)d_in[9];
    const float* bc = (const float*)d_in[10];
    const float* sc = (const float*)d_in[11];
    float* out = (float*)d_out;

    int *bufA, *bufB, *qw1, *qw2, *qw3, *qw4;
    signed char* in0;
    float *qwc, *wsc;
    cudaGetSymbolAddress((void**)&bufA, g_bufA);
    cudaGetSymbolAddress((void**)&bufB, g_bufB);
    cudaGetSymbolAddress((void**)&in0, g_in0);
    cudaGetSymbolAddress((void**)&qw1, g_qw1);
    cudaGetSymbolAddress((void**)&qw2, g_qw2);
    cudaGetSymbolAddress((void**)&qw3, g_qw3);
    cudaGetSymbolAddress((void**)&qw4, g_qw4);
    cudaGetSymbolAddress((void**)&qwc, g_qwc);
    cudaGetSymbolAddress((void**)&wsc, g_wscale);

    // weight prep (tiny)
    wquant_c1<<<1, 256>>>(w1, qw1, wsc + 0);
    wquant_pack<16, 32, 3><<<1, 256>>>(w2, qw2, wsc + 1);
    wquant_pack<32, 32, 5><<<1, 256>>>(w3, qw3, wsc + 2);
    wquant_pack<32, 16, 3><<<1, 256>>>(w4, qw4, wsc + 3);
    wquant_fc<<<1, 256>>>(wc, qwc);

    // input fake-quant to int8 codes
    inquant_kernel<<<(32 * 256 * 256 + 255) / 256, 256>>>(x, in0, sc);

    // conv1: 1->16, 3x3 valid -> bufA [32][4][254][254]
    conv1_kernel<<<dim3(2, 254, 32), 128>>>(in0, qw1, b1, bufA, sc, wsc + 0);

    // conv2: 16->32, 3x3 same -> bufB [32][8][254][254]
    conv_q_kernel<4, 32, 3, 1, 4, 8><<<dim3(2, 254, 32), 128, 4 * 9 * 32 * 4>>>(
        bufA, qw2, b2, bufB, 254, 254, 254, 254, sc, wsc + 1, 2, 3, 4);

    // conv3: 32->32, 5x5 same -> bufA
    conv_q_kernel<8, 32, 5, 2, 4, 8><<<dim3(2, 254, 32), 128, 8 * 25 * 32 * 4>>>(
        bufB, qw3, b3, bufA, 254, 254, 254, 254, sc, wsc + 2, 4, 5, 6);

    // maxpool 2x2 + requant -> bufB [32][8][127][127]
    pool_q_kernel<<<(32 * 8 * 127 * 127 + 255) / 256, 256>>>(bufA, bufB, sc);

    // conv4: 32->16, 3x3 valid -> bufA [32][4][125][125]
    conv_q_kernel<8, 16, 3, 0, 4, 4><<<dim3(1, 125, 32), 128, 8 * 9 * 16 * 4>>>(
        bufB, qw4, b4, bufA, 127, 127, 125, 125, sc, wsc + 3, 7, 8, 9);

    // global avg pool + fq(s10)
    gap_q_kernel<<<32 * 4, 256>>>(bufA, sc);

    // classifier
    fc_kernel<<<1, 512>>>(bc, out);
}

// round 5
// speedup vs baseline: 6.3663x; 1.4723x over previous
#include <cuda_runtime.h>
#include <cstdint>

#define DI __device__ __forceinline__

// exact fake-quant: clip(round-half-even(x/s), -128, 127)
DI float fq_q(float x, float s) {
    float q = rintf(__fdiv_rn(x, s));
    return fminf(fmaxf(q, -128.0f), 127.0f);
}
DI float fq(float x, float s) { return fq_q(x, s) * s; }
DI int sbyte(int w, int k) { return (int)((signed char)(w >> (8 * k))); }

// ---------------- device global scratch ----------------
__device__ signed char g_bufA[(size_t)32 * 254 * 254 * 32];   // 66 MB channel-last
__device__ signed char g_bufB[(size_t)32 * 254 * 254 * 32];   // 66 MB
__device__ signed char g_in0[(size_t)32 * 256 * 256];
__device__ int         g_qw1[9 * 16];            // [tap][oc] int codes
__device__ signed char g_qw2[9 * 32 * 16];       // [tap][oc][ic]
__device__ signed char g_qw3[25 * 32 * 32];
__device__ signed char g_qw4[9 * 16 * 32];
__device__ float g_qwc[16 * 10];
__device__ float g_wscale[8];
__device__ float g_feat[32 * 16];

// ---------------- IMMA wrappers ----------------
DI void mma_k32(int d[4], unsigned a0, unsigned a1, unsigned a2, unsigned a3,
                unsigned b0, unsigned b1) {
    asm volatile(
        "mma.sync.aligned.m16n8k32.row.col.s32.s8.s8.s32 "
        "{%0,%1,%2,%3}, {%4,%5,%6,%7}, {%8,%9}, {%0,%1,%2,%3};\n"
        : "+r"(d[0]), "+r"(d[1]), "+r"(d[2]), "+r"(d[3])
        : "r"(a0), "r"(a1), "r"(a2), "r"(a3), "r"(b0), "r"(b1));
}
DI void mma_k16(int d[4], unsigned a0, unsigned a1, unsigned b0) {
    asm volatile(
        "mma.sync.aligned.m16n8k16.row.col.s32.s8.s8.s32 "
        "{%0,%1,%2,%3}, {%4,%5}, {%6}, {%0,%1,%2,%3};\n"
        : "+r"(d[0]), "+r"(d[1]), "+r"(d[2]), "+r"(d[3])
        : "r"(a0), "r"(a1), "r"(b0));
}

DI uint2 ldg8p(const signed char* p, bool pred) {
    uint2 v = make_uint2(0u, 0u);
    if (pred) v = *(const uint2*)p;
    return v;
}
DI unsigned ldg4p(const signed char* p, bool pred) {
    unsigned v = 0u;
    if (pred) v = *(const unsigned*)p;
    return v;
}

// ---------------- input quant: fp32 -> int8 codes (planar, 1 channel) ----------------
__global__ void inquant_kernel(const float* __restrict__ x, signed char* __restrict__ out,
                               const float* __restrict__ scales) {
    int i = blockIdx.x * 256 + threadIdx.x;
    if (i < 32 * 256 * 256) out[i] = (signed char)(int)fq_q(x[i], scales[0]);
}

// ---------------- weight quant kernels ----------------
__global__ void wquant_c1(const float* __restrict__ w, int* __restrict__ dst,
                          float* __restrict__ scale_out) {
    __shared__ float red[256];
    const int n = 16 * 9;
    float m = 0.0f;
    for (int i = threadIdx.x; i < n; i += 256) m = fmaxf(m, fabsf(w[i]));
    red[threadIdx.x] = m;
    __syncthreads();
    for (int s = 128; s > 0; s >>= 1) {
        if (threadIdx.x < s) red[threadIdx.x] = fmaxf(red[threadIdx.x], red[threadIdx.x + s]);
        __syncthreads();
    }
    const float scale = __fdiv_rn(red[0], 127.0f);
    if (threadIdx.x == 0) *scale_out = scale;
    for (int i = threadIdx.x; i < n; i += 256) {
        int tap = i % 9, oc = i / 9;
        dst[tap * 16 + oc] = (int)fq_q(w[i], scale);
    }
}

// dst[(tap*OC + oc)*IC + ic] bytes, src w[oc][ic][ky][kx]
template <int IC, int OC, int K>
__global__ void wquant_mma(const float* __restrict__ w, signed char* __restrict__ dst,
                           float* __restrict__ scale_out) {
    __shared__ float red[256];
    const int n = OC * IC * K * K;
    float m = 0.0f;
    for (int i = threadIdx.x; i < n; i += 256) m = fmaxf(m, fabsf(w[i]));
    red[threadIdx.x] = m;
    __syncthreads();
    for (int s = 128; s > 0; s >>= 1) {
        if (threadIdx.x < s) red[threadIdx.x] = fmaxf(red[threadIdx.x], red[threadIdx.x + s]);
        __syncthreads();
    }
    const float scale = __fdiv_rn(red[0], 127.0f);
    if (threadIdx.x == 0) *scale_out = scale;
    for (int i = threadIdx.x; i < n; i += 256) {
        int ic  = i % IC;
        int oc  = (i / IC) % OC;
        int tap = i / (IC * OC);
        int ky = tap / K, kx = tap % K;
        dst[i] = (signed char)(int)fq_q(w[((oc * IC + ic) * K + ky) * K + kx], scale);
    }
}

__global__ void wquant_fc(const float* __restrict__ w, float* __restrict__ dst) {
    __shared__ float red[256];
    const int n = 160;
    float m = 0.0f;
    for (int i = threadIdx.x; i < n; i += 256) m = fmaxf(m, fabsf(w[i]));
    red[threadIdx.x] = m;
    __syncthreads();
    for (int s = 128; s > 0; s >>= 1) {
        if (threadIdx.x < s) red[threadIdx.x] = fmaxf(red[threadIdx.x], red[threadIdx.x + s]);
        __syncthreads();
    }
    const float scale = __fdiv_rn(red[0], 127.0f);
    for (int i = threadIdx.x; i < n; i += 256) {
        int ic = i % 16, oc = i / 16;
        dst[ic * 10 + oc] = fq_q(w[i], scale) * scale;
    }
}

// ---------------- conv1: 1->16 3x3 valid, scalar IMAD, channel-last out ----------------
__global__ void __launch_bounds__(256) conv1_kernel(
    const signed char* __restrict__ in, const int* __restrict__ wq,
    const float* __restrict__ bias, signed char* __restrict__ out,
    const float* __restrict__ scales, const float* __restrict__ wscale) {
    __shared__ int wsm[144];
    __shared__ signed char lut[256];
    __shared__ float bsm[16];
    const int tid = threadIdx.x;
    const float sa = scales[1], sb = scales[2];
    if (tid < 256) lut[tid] = (signed char)(int)fq_q((float)(tid - 128) * sa, sb);
    if (tid < 144) wsm[tid] = wq[tid];
    if (tid < 16) bsm[tid] = bias[tid];
    __syncthreads();

    int idx = blockIdx.x * 256 + tid;
    if (idx >= 32 * 254 * 254) return;
    int x = idx % 254, y = (idx / 254) % 254, b = idx / (254 * 254);

    const signed char* base = in + (size_t)b * 256 * 256;
    int v[9];
#pragma unroll
    for (int ky = 0; ky < 3; ky++)
#pragma unroll
        for (int kx = 0; kx < 3; kx++)
            v[ky * 3 + kx] = (int)base[(size_t)(y + ky) * 256 + (x + kx)];

    int acc[16];
#pragma unroll
    for (int j = 0; j < 16; j++) acc[j] = 0;
#pragma unroll
    for (int tap = 0; tap < 9; tap++)
#pragma unroll
        for (int j = 0; j < 16; j++) acc[j] += v[tap] * wsm[tap * 16 + j];

    const float cs = scales[0] * wscale[0];
    unsigned wds[4];
#pragma unroll
    for (int g = 0; g < 4; g++) {
        unsigned wd = 0;
#pragma unroll
        for (int k = 0; k < 4; k++) {
            int j = g * 4 + k;
            float r = fmaf((float)acc[j], cs, bsm[j]);
            r = fmaxf(r, 0.0f);
            int c1 = (int)fq_q(r, sa);
            wd |= ((unsigned)(unsigned char)lut[c1 + 128]) << (8 * k);
        }
        wds[g] = wd;
    }
    *(uint4*)(out + (size_t)idx * 16) = make_uint4(wds[0], wds[1], wds[2], wds[3]);
}

// ---------------- generic IMMA conv (channel-last in/out) ----------------
// CTA covers 128 output x at one (y, b). OC=32: 8 warps (256t); OC=16: 4 warps (128t).
// warp: mpair = warp/NHALF -> 32 px; nhalf = warp%NHALF -> 16 oc.
template <int ICB, int OC, int K, int PAD>
__global__ void __launch_bounds__(256 * (OC / 16) / 2) conv_mma_kernel(
    const signed char* __restrict__ in, const signed char* __restrict__ wq,
    const float* __restrict__ bias, signed char* __restrict__ out,
    int Hin, int Win, int Hout, int Wout,
    const float* __restrict__ scales, const float* __restrict__ wscale,
    int s_in, int s_a, int s_b) {
    constexpr int NHALF = OC / 16;
    constexpr int NT = 128 * NHALF;        // 256 or 128 threads
    constexpr int NWB = K * K * OC * ICB;  // weight bytes

    __shared__ int wsm[NWB / 4];
    __shared__ signed char lut[256];
    __shared__ signed char stg[128 * OC];

    const int tid = threadIdx.x;
    const int warp = tid >> 5, lane = tid & 31;
    const int g = lane >> 2, t = lane & 3;
    const int mpair = warp / NHALF;
    const int nhalf = warp % NHALF;

    const float sa = scales[s_a], sb = scales[s_b];
    for (int i = tid; i < 256; i += NT)
        lut[i] = (signed char)(int)fq_q((float)(i - 128) * sa, sb);
    for (int i = tid; i < NWB / 4; i += NT) wsm[i] = ((const int*)wq)[i];
    __syncthreads();

    const int bx = blockIdx.x, y = blockIdx.y, b = blockIdx.z;
    const int xbase = bx * 128 + mpair * 32;
    const signed char* inb = in + (size_t)b * Hin * Win * ICB;
    const signed char* wsb = (const signed char*)wsm;

    int acc[2][2][4];
#pragma unroll
    for (int m = 0; m < 2; m++)
#pragma unroll
        for (int nt = 0; nt < 2; nt++)
#pragma unroll
            for (int k = 0; k < 4; k++) acc[m][nt][k] = 0;

#pragma unroll
    for (int ky = 0; ky < K; ky++) {
        const int iy = y + ky - PAD;
        const bool vy = (unsigned)iy < (unsigned)Hin;
        const signed char* rowp = inb + (long)iy * Win * ICB;
#pragma unroll
        for (int kx = 0; kx < K; kx++) {
            const int tap = ky * K + kx;
            if constexpr (ICB == 32) {
                uint2 A[2][2];
#pragma unroll
                for (int m = 0; m < 2; m++) {
                    int xA = xbase + m * 16 + g + kx - PAD;
                    int xB = xA + 8;
                    A[m][0] = ldg8p(rowp + (long)xA * 32 + 8 * t, vy && (unsigned)xA < (unsigned)Win);
                    A[m][1] = ldg8p(rowp + (long)xB * 32 + 8 * t, vy && (unsigned)xB < (unsigned)Win);
                }
#pragma unroll
                for (int nt = 0; nt < 2; nt++) {
                    uint2 B = *(const uint2*)(wsb + (tap * OC + nhalf * 16 + nt * 8 + g) * 32 + 8 * t);
#pragma unroll
                    for (int m = 0; m < 2; m++)
                        mma_k32(acc[m][nt], A[m][0].x, A[m][1].x, A[m][0].y, A[m][1].y, B.x, B.y);
                }
            } else {  // ICB == 16
                unsigned A[2][2];
#pragma unroll
                for (int m = 0; m < 2; m++) {
                    int xA = xbase + m * 16 + g + kx - PAD;
                    int xB = xA + 8;
                    A[m][0] = ldg4p(rowp + (long)xA * 16 + 4 * t, vy && (unsigned)xA < (unsigned)Win);
                    A[m][1] = ldg4p(rowp + (long)xB * 16 + 4 * t, vy && (unsigned)xB < (unsigned)Win);
                }
#pragma unroll
                for (int nt = 0; nt < 2; nt++) {
                    unsigned B = *(const unsigned*)(wsb + (tap * OC + nhalf * 16 + nt * 8 + g) * 16 + 4 * t);
#pragma unroll
                    for (int m = 0; m < 2; m++)
                        mma_k16(acc[m][nt], A[m][0], A[m][1], B);
                }
            }
        }
    }

    // epilogue: fq chain -> int8 codes in smem, then coalesced STG.128
    const float cs = scales[s_in] * wscale[0];
    float bv[2][2];
#pragma unroll
    for (int nt = 0; nt < 2; nt++) {
        bv[nt][0] = bias[nhalf * 16 + nt * 8 + 2 * t];
        bv[nt][1] = bias[nhalf * 16 + nt * 8 + 2 * t + 1];
    }
#pragma unroll
    for (int m = 0; m < 2; m++)
#pragma unroll
        for (int r = 0; r < 2; r++) {
            const int px = mpair * 32 + m * 16 + r * 8 + g;
#pragma unroll
            for (int nt = 0; nt < 2; nt++) {
                float r0 = fmaf((float)acc[m][nt][2 * r + 0], cs, bv[nt][0]);
                float r1 = fmaf((float)acc[m][nt][2 * r + 1], cs, bv[nt][1]);
                r0 = fmaxf(r0, 0.0f);
                r1 = fmaxf(r1, 0.0f);
                int c1a = (int)fq_q(r0, sa);
                int c1b = (int)fq_q(r1, sa);
                unsigned short pk = (unsigned short)((unsigned char)lut[c1a + 128] |
                                    ((unsigned)(unsigned char)lut[c1b + 128] << 8));
                *(unsigned short*)(stg + px * OC + nhalf * 16 + nt * 8 + 2 * t) = pk;
            }
        }
    __syncthreads();

    // cooperative vector store: NT threads x 16B = 128*OC bytes
    {
        const int i = tid;
        const int px = (16 * i) / OC;
        if (bx * 128 + px < Wout) {
            signed char* dst = out + (((size_t)(b * Hout + y)) * Wout + bx * 128) * OC + 16 * i;
            *(int4*)dst = *(const int4*)(stg + 16 * i);
        }
    }
}

// ---------------- maxpool 2x2 bytewise + LUT requant (channel-last 32c) ----------------
__global__ void pool_kernel(const signed char* __restrict__ in, signed char* __restrict__ out,
                            const float* __restrict__ scales) {
    __shared__ signed char lut[256];
    const int tid = threadIdx.x;
    const float s6 = scales[6], s7 = scales[7];
    if (tid < 256) lut[tid] = (signed char)(int)fq_q((float)(tid - 128) * s6, s7);
    __syncthreads();

    int idx = blockIdx.x * 256 + tid;
    const int total = 32 * 127 * 127 * 2;
    if (idx >= total) return;
    int half = idx & 1;
    int p = idx >> 1;
    int x = p % 127, y = (p / 127) % 127, b = p / (127 * 127);

    const signed char* src = in + (((size_t)(b * 254 + 2 * y)) * 254 + 2 * x) * 32 + half * 16;
    int4 v00 = *(const int4*)src;
    int4 v01 = *(const int4*)(src + 32);
    int4 v10 = *(const int4*)(src + 254 * 32);
    int4 v11 = *(const int4*)(src + 254 * 32 + 32);
    int mw[4];
    mw[0] = __vmaxs4(__vmaxs4(v00.x, v01.x), __vmaxs4(v10.x, v11.x));
    mw[1] = __vmaxs4(__vmaxs4(v00.y, v01.y), __vmaxs4(v10.y, v11.y));
    mw[2] = __vmaxs4(__vmaxs4(v00.z, v01.z), __vmaxs4(v10.z, v11.z));
    mw[3] = __vmaxs4(__vmaxs4(v00.w, v01.w), __vmaxs4(v10.w, v11.w));

    unsigned rw[4];
#pragma unroll
    for (int w = 0; w < 4; w++) {
        unsigned r = 0;
#pragma unroll
        for (int k = 0; k < 4; k++)
            r |= ((unsigned)(unsigned char)lut[sbyte(mw[w], k) + 128]) << (8 * k);
        rw[w] = r;
    }
    *(uint4*)(out + (((size_t)(b * 127 + y)) * 127 + x) * 32 + half * 16) =
        make_uint4(rw[0], rw[1], rw[2], rw[3]);
}

// ---------------- global avg pool (channel-last 16c) + fq(s10) ----------------
__global__ void gap_kernel(const signed char* __restrict__ in, const float* __restrict__ scales) {
    __shared__ int red[256][16];
    const int b = blockIdx.x, tid = threadIdx.x;
    int acc[16];
#pragma unroll
    for (int k = 0; k < 16; k++) acc[k] = 0;
    const signed char* p = in + (size_t)b * 125 * 125 * 16;
    for (int i = tid; i < 125 * 125; i += 256) {
        int4 v = *(const int4*)(p + (size_t)i * 16);
        int w[4] = {v.x, v.y, v.z, v.w};
#pragma unroll
        for (int j = 0; j < 4; j++)
#pragma unroll
            for (int k = 0; k < 4; k++) acc[j * 4 + k] += sbyte(w[j], k);
    }
#pragma unroll
    for (int k = 0; k < 16; k++) red[tid][k] = acc[k];
    __syncthreads();
    for (int s = 128; s > 0; s >>= 1) {
        if (tid < s)
#pragma unroll
            for (int k = 0; k < 16; k++) red[tid][k] += red[tid + s][k];
        __syncthreads();
    }
    if (tid < 16) {
        float mean = __fdiv_rn((float)red[0][tid] * scales[9], 15625.0f);
        g_feat[b * 16 + tid] = fq(mean, scales[10]);
    }
}

// ---------------- classifier ----------------
__global__ void fc_kernel(const float* __restrict__ bias, float* __restrict__ out) {
    int tt = threadIdx.x;
    if (tt >= 320) return;
    int b = tt / 10, j = tt % 10;
    float s = bias[j];
#pragma unroll
    for (int k = 0; k < 16; k++) s += g_feat[b * 16 + k] * g_qwc[k * 10 + j];
    out[b * 10 + j] = s;
}

// ---------------- launcher ----------------
extern "C" void kernel_launch(void* const* d_in, const int* in_sizes, int n_in,
                              void* d_out, int out_size) {
    const float* x  = (const float*)d_in[0];
    const float* w1 = (const float*)d_in[1];
    const float* b1 = (const float*)d_in[2];
    const float* w2 = (const float*)d_in[3];
    const float* b2 = (const float*)d_in[4];
    const float* w3 = (const float*)d_in[5];
    const float* b3 = (const float*)d_in[6];
    const float* w4 = (const float*)d_in[7];
    const float* b4 = (const float*)d_in[8];
    const float* wc = (const float*)d_in[9];
    const float* bc = (const float*)d_in[10];
    const float* sc = (const float*)d_in[11];
    float* out = (float*)d_out;

    signed char *bufA, *bufB, *in0, *qw2, *qw3, *qw4;
    int* qw1;
    float *qwc, *wsc;
    cudaGetSymbolAddress((void**)&bufA, g_bufA);
    cudaGetSymbolAddress((void**)&bufB, g_bufB);
    cudaGetSymbolAddress((void**)&in0, g_in0);
    cudaGetSymbolAddress((void**)&qw1, g_qw1);
    cudaGetSymbolAddress((void**)&qw2, g_qw2);
    cudaGetSymbolAddress((void**)&qw3, g_qw3);
    cudaGetSymbolAddress((void**)&qw4, g_qw4);
    cudaGetSymbolAddress((void**)&qwc, g_qwc);
    cudaGetSymbolAddress((void**)&wsc, g_wscale);

    // weight prep (tiny)
    wquant_c1<<<1, 256>>>(w1, qw1, wsc + 0);
    wquant_mma<16, 32, 3><<<1, 256>>>(w2, qw2, wsc + 1);
    wquant_mma<32, 32, 5><<<1, 256>>>(w3, qw3, wsc + 2);
    wquant_mma<32, 16, 3><<<1, 256>>>(w4, qw4, wsc + 3);
    wquant_fc<<<1, 256>>>(wc, qwc);

    // input fake-quant
    inquant_kernel<<<(32 * 256 * 256 + 255) / 256, 256>>>(x, in0, sc);

    // conv1: 1->16 valid -> bufA [b][254][254][16]
    conv1_kernel<<<(32 * 254 * 254 + 255) / 256, 256>>>(in0, qw1, b1, bufA, sc, wsc + 0);

    // conv2: 16->32 same -> bufB [b][254][254][32]
    conv_mma_kernel<16, 32, 3, 1><<<dim3(2, 254, 32), 256>>>(
        bufA, qw2, b2, bufB, 254, 254, 254, 254, sc, wsc + 1, 2, 3, 4);

    // conv3: 32->32 5x5 same -> bufA [b][254][254][32]
    conv_mma_kernel<32, 32, 5, 2><<<dim3(2, 254, 32), 256>>>(
        bufB, qw3, b3, bufA, 254, 254, 254, 254, sc, wsc + 2, 4, 5, 6);

    // maxpool 2x2 + LUT requant -> bufB [b][127][127][32]
    pool_kernel<<<(32 * 127 * 127 * 2 + 255) / 256, 256>>>(bufA, bufB, sc);

    // conv4: 32->16 valid -> bufA [b][125][125][16]
    conv_mma_kernel<32, 16, 3, 0><<<dim3(1, 125, 32), 128>>>(
        bufB, qw4, b4, bufA, 127, 127, 125, 125, sc, wsc + 3, 7, 8, 9);

    // global avg pool + fq(s10)
    gap_kernel<<<32, 256>>>(bufA, sc);

    // classifier
    fc_kernel<<<1, 512>>>(bc, out);
}

// round 6
// speedup vs baseline: 6.9901x; 1.0980x over previous
#include <cuda_runtime.h>
#include <cstdint>

#define DI __device__ __forceinline__

// exact fake-quant (used only in low-volume paths)
DI float fq_q(float x, float s) {
    float q = rintf(__fdiv_rn(x, s));
    return fminf(fmaxf(q, -128.0f), 127.0f);
}
DI float fq(float x, float s) { return fq_q(x, s) * s; }
DI int sbyte(int w, int k) { return (int)((signed char)(w >> (8 * k))); }

// ---------------- padded layout constants ----------------
// padded act buffers: 260 rows x 264 cols, logical (0,0) at (+3,+3)
#define WSP 264
#define HSP 260
#define ORG (3 * 264 + 3)

// ---------------- device global scratch ----------------
__device__ __align__(16) signed char g_bufA[(size_t)32 * 254 * 254 * 32];  // 66 MB
__device__ __align__(16) signed char g_bufB[(size_t)32 * HSP * WSP * 32];  // 70 MB
__device__ __align__(16) signed char g_in0[(size_t)32 * 256 * 256];
__device__ __align__(16) int         g_qw1[9 * 16];        // [tap][oc]
__device__ __align__(16) signed char g_qw2[9 * 32 * 16];   // [tap][oc][ic]
__device__ __align__(16) signed char g_qw3[25 * 32 * 32];
__device__ __align__(16) signed char g_qw4[9 * 16 * 32];
__device__ float g_qwc[16 * 10];
__device__ float g_wscale[8];
__device__ float g_feat[32 * 16];

// ---------------- IMMA wrappers ----------------
DI void mma_k32(int d[4], unsigned a0, unsigned a1, unsigned a2, unsigned a3,
                unsigned b0, unsigned b1) {
    asm volatile(
        "mma.sync.aligned.m16n8k32.row.col.s32.s8.s8.s32 "
        "{%0,%1,%2,%3}, {%4,%5,%6,%7}, {%8,%9}, {%0,%1,%2,%3};\n"
        : "+r"(d[0]), "+r"(d[1]), "+r"(d[2]), "+r"(d[3])
        : "r"(a0), "r"(a1), "r"(a2), "r"(a3), "r"(b0), "r"(b1));
}
DI void mma_k16(int d[4], unsigned a0, unsigned a1, unsigned b0) {
    asm volatile(
        "mma.sync.aligned.m16n8k16.row.col.s32.s8.s8.s32 "
        "{%0,%1,%2,%3}, {%4,%5}, {%6}, {%0,%1,%2,%3};\n"
        : "+r"(d[0]), "+r"(d[1]), "+r"(d[2]), "+r"(d[3])
        : "r"(a0), "r"(a1), "r"(b0));
}

// ---------------- halo zero: rings of padded buffers ----------------
// per batch: 4124 halo px (rows 0-2,257-259 full width; cols 0-2,257-263 of mid rows)
__global__ void halo_kernel(signed char* bufA16, signed char* bufB32) {
    const int ITEMS = 32 * 4124;
    int idx = blockIdx.x * 256 + threadIdx.x;
    int which = 0;
    if (idx >= ITEMS) { idx -= ITEMS; which = 1; }
    if (idx >= ITEMS) return;
    int b = idx / 4124, i = idx % 4124;
    int prow, pcol;
    if (i < 1584) {
        int pr = i / 264;
        pcol = i % 264;
        prow = (pr < 3) ? pr : 257 + (pr - 3);
    } else {
        int j = i - 1584;
        prow = 3 + j / 10;
        int pc = j % 10;
        pcol = (pc < 3) ? pc : 257 + (pc - 3);
    }
    size_t px = ((size_t)b * HSP + prow) * WSP + pcol;
    uint4 z = make_uint4(0, 0, 0, 0);
    if (which == 0) {
        *(uint4*)(bufA16 + px * 16) = z;
    } else {
        *(uint4*)(bufB32 + px * 32) = z;
        *(uint4*)(bufB32 + px * 32 + 16) = z;
    }
}

// ---------------- fused weight quant: 5 blocks ----------------
DI float blockmax_abs(const float* w, int n, float* red) {
    float m = 0.0f;
    for (int i = threadIdx.x; i < n; i += 256) m = fmaxf(m, fabsf(w[i]));
    red[threadIdx.x] = m;
    __syncthreads();
    for (int s = 128; s > 0; s >>= 1) {
        if (threadIdx.x < s) red[threadIdx.x] = fmaxf(red[threadIdx.x], red[threadIdx.x + s]);
        __syncthreads();
    }
    return red[0];
}

__global__ void wquant_all(const float* __restrict__ w1, const float* __restrict__ w2,
                           const float* __restrict__ w3, const float* __restrict__ w4,
                           const float* __restrict__ wc,
                           int* qw1, signed char* qw2, signed char* qw3, signed char* qw4,
                           float* qwc, float* wsc) {
    __shared__ float red[256];
    const int bid = blockIdx.x, tid = threadIdx.x;
    if (bid == 0) {
        float scale = __fdiv_rn(blockmax_abs(w1, 144, red), 127.0f);
        if (tid == 0) wsc[0] = scale;
        for (int i = tid; i < 144; i += 256) {
            int tap = i % 9, oc = i / 9;
            qw1[tap * 16 + oc] = (int)fq_q(w1[i], scale);
        }
    } else if (bid == 1) {
        float scale = __fdiv_rn(blockmax_abs(w2, 4608, red), 127.0f);
        if (tid == 0) wsc[1] = scale;
        for (int i = tid; i < 4608; i += 256) {
            int ic = i % 16, oc = (i / 16) % 32, tap = i / (16 * 32);
            int ky = tap / 3, kx = tap % 3;
            qw2[i] = (signed char)(int)fq_q(w2[((oc * 16 + ic) * 3 + ky) * 3 + kx], scale);
        }
    } else if (bid == 2) {
        float scale = __fdiv_rn(blockmax_abs(w3, 25600, red), 127.0f);
        if (tid == 0) wsc[2] = scale;
        for (int i = tid; i < 25600; i += 256) {
            int ic = i % 32, oc = (i / 32) % 32, tap = i / (32 * 32);
            int ky = tap / 5, kx = tap % 5;
            qw3[i] = (signed char)(int)fq_q(w3[((oc * 32 + ic) * 5 + ky) * 5 + kx], scale);
        }
    } else if (bid == 3) {
        float scale = __fdiv_rn(blockmax_abs(w4, 4608, red), 127.0f);
        if (tid == 0) wsc[3] = scale;
        for (int i = tid; i < 4608; i += 256) {
            int ic = i % 32, oc = (i / 32) % 16, tap = i / (32 * 16);
            int ky = tap / 3, kx = tap % 3;
            qw4[i] = (signed char)(int)fq_q(w4[((oc * 32 + ic) * 3 + ky) * 3 + kx], scale);
        }
    } else {
        float scale = __fdiv_rn(blockmax_abs(wc, 160, red), 127.0f);
        for (int i = tid; i < 160; i += 256) {
            int ic = i % 16, oc = i / 16;
            qwc[ic * 10 + oc] = fq_q(wc[i], scale) * scale;
        }
    }
}

// ---------------- input quant: fp32 -> packed int8 codes ----------------
__global__ void inquant_kernel(const float* __restrict__ x, int* __restrict__ out,
                               const float* __restrict__ scales) {
    int i = blockIdx.x * 256 + threadIdx.x;
    if (i >= 32 * 256 * 256 / 4) return;
    float4 v = ((const float4*)x)[i];
    float inv = __frcp_rn(scales[0]);    // 1/s0, correctly rounded reciprocal
    int c0 = max(min(__float2int_rn(v.x * inv), 127), -128);
    int c1 = max(min(__float2int_rn(v.y * inv), 127), -128);
    int c2 = max(min(__float2int_rn(v.z * inv), 127), -128);
    int c3 = max(min(__float2int_rn(v.w * inv), 127), -128);
    out[i] = (c0 & 0xFF) | ((c1 & 0xFF) << 8) | ((c2 & 0xFF) << 16) | ((c3 & 0xFF) << 24);
}

// ---------------- conv1: 1->16 3x3 valid, scalar IMAD, padded16 out ----------------
__global__ void __launch_bounds__(256) conv1_kernel(
    const signed char* __restrict__ in, const int* __restrict__ wq,
    const float* __restrict__ bias, signed char* __restrict__ out,
    const float* __restrict__ scales, const float* __restrict__ wscale) {
    __shared__ int wsm[144];
    __shared__ signed char lut[128];
    __shared__ float bsm[16];
    const int tid = threadIdx.x;
    const float sa = scales[1], sb = scales[2];
    if (tid < 128) lut[tid] = (signed char)(int)fq_q((float)tid * sa, sb);
    if (tid < 144) wsm[tid] = wq[tid];
    if (tid >= 144 && tid < 160) bsm[tid - 144] = bias[tid - 144];
    __syncthreads();

    int idx = blockIdx.x * 256 + tid;
    if (idx >= 32 * 254 * 254) return;
    int x = idx % 254, y = (idx / 254) % 254, b = idx / (254 * 254);

    const signed char* base = in + (size_t)b * 256 * 256;
    int v[9];
#pragma unroll
    for (int ky = 0; ky < 3; ky++)
#pragma unroll
        for (int kx = 0; kx < 3; kx++)
            v[ky * 3 + kx] = (int)base[(size_t)(y + ky) * 256 + (x + kx)];

    int acc[16];
#pragma unroll
    for (int j = 0; j < 16; j++) acc[j] = 0;
#pragma unroll
    for (int tap = 0; tap < 9; tap++)
#pragma unroll
        for (int j = 0; j < 16; j++) acc[j] += v[tap] * wsm[tap * 16 + j];

    const float csa = __fdiv_rn(scales[0] * wscale[0], sa);
    unsigned wds[4];
#pragma unroll
    for (int g = 0; g < 4; g++) {
        unsigned wd = 0;
#pragma unroll
        for (int k = 0; k < 4; k++) {
            int j = g * 4 + k;
            float bva = __fdiv_rn(bsm[j], sa);
            int c1 = __float2int_rn(fmaf((float)acc[j], csa, bva));
            c1 = max(min(c1, 127), 0);
            wd |= ((unsigned)(unsigned char)lut[c1]) << (8 * k);
        }
        wds[g] = wd;
    }
    size_t px = ((size_t)b * HSP + (y + 3)) * WSP + (x + 3);
    *(uint4*)(out + px * 16) = make_uint4(wds[0], wds[1], wds[2], wds[3]);
}

// ---------------- lean IMMA conv ----------------
// 4 warps/CTA; warp w owns px [w*32, w*32+32) x all OC. Unconditional LDG (padded in).
template <int ICB, int OC, int K, int PAD>
__global__ void __launch_bounds__(128) conv_mma_kernel(
    const signed char* __restrict__ in, long BSi, int RSi,
    const signed char* __restrict__ wq, const float* __restrict__ bias,
    signed char* __restrict__ out, long BSo, int RSo, int Wout,
    const float* __restrict__ scales, const float* __restrict__ wscale,
    int s_in, int s_a, int s_b) {
    constexpr int NTL = OC / 8;            // n-tiles per warp
    constexpr int NWB = K * K * OC * ICB;  // weight bytes

    __shared__ int wsm[NWB / 4];
    __shared__ signed char lut[128];
    __shared__ signed char stg[128 * OC];

    const int tid = threadIdx.x;
    const int w = tid >> 5, lane = tid & 31;
    const int g = lane >> 2, t = lane & 3;

    const float sa = scales[s_a], sb = scales[s_b];
    if (tid < 128) lut[tid] = (signed char)(int)fq_q((float)tid * sa, sb);
    for (int i = tid; i < NWB / 4; i += 128) wsm[i] = ((const int*)wq)[i];
    __syncthreads();

    const int bx = blockIdx.x, y = blockIdx.y, b = blockIdx.z;
    const int xw = bx * 128 + w * 32;
    const signed char* wsb = (const signed char*)wsm;

    int acc[2][NTL][4];
#pragma unroll
    for (int m = 0; m < 2; m++)
#pragma unroll
        for (int nt = 0; nt < NTL; nt++)
#pragma unroll
            for (int k = 0; k < 4; k++) acc[m][nt][k] = 0;

#pragma unroll
    for (int ky = 0; ky < K; ky++) {
        const signed char* rp =
            in + ((long)b * BSi + (long)(y + ky - PAD) * RSi + (xw - PAD)) * ICB;
#pragma unroll
        for (int kx = 0; kx < K; kx++) {
            const int tap = ky * K + kx;
            if constexpr (ICB == 32) {
                uint2 A[2][2];
#pragma unroll
                for (int m = 0; m < 2; m++) {
                    const signed char* p = rp + kx * 32 + (m * 16 + g) * 32 + 8 * t;
                    A[m][0] = *(const uint2*)p;
                    A[m][1] = *(const uint2*)(p + 8 * 32);
                }
#pragma unroll
                for (int nt = 0; nt < NTL; nt++) {
                    uint2 B = *(const uint2*)(wsb + ((tap * OC) + nt * 8 + g) * 32 + 8 * t);
#pragma unroll
                    for (int m = 0; m < 2; m++)
                        mma_k32(acc[m][nt], A[m][0].x, A[m][1].x, A[m][0].y, A[m][1].y,
                                B.x, B.y);
                }
            } else {  // ICB == 16, k16 MMA
                unsigned A[2][2];
#pragma unroll
                for (int m = 0; m < 2; m++) {
                    const signed char* p = rp + kx * 16 + (m * 16 + g) * 16 + 4 * t;
                    A[m][0] = *(const unsigned*)p;
                    A[m][1] = *(const unsigned*)(p + 8 * 16);
                }
#pragma unroll
                for (int nt = 0; nt < NTL; nt++) {
                    unsigned B = *(const unsigned*)(wsb + ((tap * OC) + nt * 8 + g) * 16 + 4 * t);
#pragma unroll
                    for (int m = 0; m < 2; m++) mma_k16(acc[m][nt], A[m][0], A[m][1], B);
                }
            }
        }
    }

    // epilogue: c1 = clamp(rni(acc*cs' + b'), 0, 127); byte = lut[c1]
    const float csa = __fdiv_rn(scales[s_in] * wscale[0], sa);
    float bva[NTL][2];
#pragma unroll
    for (int nt = 0; nt < NTL; nt++) {
        bva[nt][0] = __fdiv_rn(bias[nt * 8 + 2 * t], sa);
        bva[nt][1] = __fdiv_rn(bias[nt * 8 + 2 * t + 1], sa);
    }
#pragma unroll
    for (int m = 0; m < 2; m++)
#pragma unroll
        for (int r = 0; r < 2; r++) {
            const int px = w * 32 + m * 16 + r * 8 + g;
#pragma unroll
            for (int nt = 0; nt < NTL; nt++) {
                int c0 = __float2int_rn(fmaf((float)acc[m][nt][2 * r + 0], csa, bva[nt][0]));
                int c1 = __float2int_rn(fmaf((float)acc[m][nt][2 * r + 1], csa, bva[nt][1]));
                c0 = max(min(c0, 127), 0);
                c1 = max(min(c1, 127), 0);
                unsigned short pk = (unsigned short)((unsigned char)lut[c0] |
                                    ((unsigned)(unsigned char)lut[c1] << 8));
                *(unsigned short*)(stg + px * OC + nt * 8 + 2 * t) = pk;
            }
        }
    __syncthreads();

    // cooperative vector store
#pragma unroll
    for (int i = tid; i < 128 * OC / 16; i += 128) {
        const int px = (16 * i) / OC;
        if (bx * 128 + px < Wout) {
            signed char* dst = out + ((long)b * BSo + (long)y * RSo + bx * 128) * OC + 16 * i;
            *(uint4*)dst = *(const uint4*)(stg + 16 * i);
        }
    }
}

// ---------------- maxpool 2x2 + LUT requant: compact32 in -> pool-padded out ----------------
__global__ void pool_kernel(const signed char* __restrict__ in, signed char* __restrict__ out,
                            const float* __restrict__ scales) {
    __shared__ signed char lut[128];
    const int tid = threadIdx.x;
    const float s6 = scales[6], s7 = scales[7];
    if (tid < 128) lut[tid] = (signed char)(int)fq_q((float)tid * s6, s7);
    __syncthreads();

    int idx = blockIdx.x * 256 + tid;
    const int total = 32 * 127 * 127 * 2;
    if (idx >= total) return;
    int half = idx & 1;
    int p = idx >> 1;
    int x = p % 127, y = (p / 127) % 127, b = p / (127 * 127);

    const signed char* src = in + (((size_t)(b * 254 + 2 * y)) * 254 + 2 * x) * 32 + half * 16;
    int4 v00 = *(const int4*)src;
    int4 v01 = *(const int4*)(src + 32);
    int4 v10 = *(const int4*)(src + 254 * 32);
    int4 v11 = *(const int4*)(src + 254 * 32 + 32);
    int mw[4];
    mw[0] = __vmaxs4(__vmaxs4(v00.x, v01.x), __vmaxs4(v10.x, v11.x));
    mw[1] = __vmaxs4(__vmaxs4(v00.y, v01.y), __vmaxs4(v10.y, v11.y));
    mw[2] = __vmaxs4(__vmaxs4(v00.z, v01.z), __vmaxs4(v10.z, v11.z));
    mw[3] = __vmaxs4(__vmaxs4(v00.w, v01.w), __vmaxs4(v10.w, v11.w));

    unsigned rw[4];
#pragma unroll
    for (int ww = 0; ww < 4; ww++) {
        unsigned r = 0;
#pragma unroll
        for (int k = 0; k < 4; k++)
            r |= ((unsigned)(unsigned char)lut[sbyte(mw[ww], k)]) << (8 * k);
        rw[ww] = r;
    }
    *(uint4*)(out + (((size_t)(b * 127 + y)) * 132 + x) * 32 + half * 16) =
        make_uint4(rw[0], rw[1], rw[2], rw[3]);
}

// ---------------- global avg pool (compact16 in) + fq(s10) ----------------
__global__ void gap_kernel(const signed char* __restrict__ in, const float* __restrict__ scales) {
    __shared__ int red[256][16];
    const int b = blockIdx.x, tid = threadIdx.x;
    int acc[16];
#pragma unroll
    for (int k = 0; k < 16; k++) acc[k] = 0;
    const signed char* p = in + (size_t)b * 125 * 125 * 16;
    for (int i = tid; i < 125 * 125; i += 256) {
        int4 v = *(const int4*)(p + (size_t)i * 16);
        int wv[4] = {v.x, v.y, v.z, v.w};
#pragma unroll
        for (int j = 0; j < 4; j++)
#pragma unroll
            for (int k = 0; k < 4; k++) acc[j * 4 + k] += sbyte(wv[j], k);
    }
#pragma unroll
    for (int k = 0; k < 16; k++) red[tid][k] = acc[k];
    __syncthreads();
    for (int s = 128; s > 0; s >>= 1) {
        if (tid < s)
#pragma unroll
            for (int k = 0; k < 16; k++) red[tid][k] += red[tid + s][k];
        __syncthreads();
    }
    if (tid < 16) {
        float mean = __fdiv_rn((float)red[0][tid] * scales[9], 15625.0f);
        g_feat[b * 16 + tid] = fq(mean, scales[10]);
    }
}

// ---------------- classifier ----------------
__global__ void fc_kernel(const float* __restrict__ bias, float* __restrict__ out) {
    int tt = threadIdx.x;
    if (tt >= 320) return;
    int b = tt / 10, j = tt % 10;
    float s = bias[j];
#pragma unroll
    for (int k = 0; k < 16; k++) s += g_feat[b * 16 + k] * g_qwc[k * 10 + j];
    out[b * 10 + j] = s;
}

// ---------------- launcher ----------------
extern "C" void kernel_launch(void* const* d_in, const int* in_sizes, int n_in,
                              void* d_out, int out_size) {
    const float* x  = (const float*)d_in[0];
    const float* w1 = (const float*)d_in[1];
    const float* b1 = (const float*)d_in[2];
    const float* w2 = (const float*)d_in[3];
    const float* b2 = (const float*)d_in[4];
    const float* w3 = (const float*)d_in[5];
    const float* b3 = (const float*)d_in[6];
    const float* w4 = (const float*)d_in[7];
    const float* b4 = (const float*)d_in[8];
    const float* wc = (const float*)d_in[9];
    const float* bc = (const float*)d_in[10];
    const float* sc = (const float*)d_in[11];
    float* out = (float*)d_out;

    signed char *bufA, *bufB, *in0, *qw2, *qw3, *qw4;
    int* qw1;
    float *qwc, *wsc;
    cudaGetSymbolAddress((void**)&bufA, g_bufA);
    cudaGetSymbolAddress((void**)&bufB, g_bufB);
    cudaGetSymbolAddress((void**)&in0, g_in0);
    cudaGetSymbolAddress((void**)&qw1, g_qw1);
    cudaGetSymbolAddress((void**)&qw2, g_qw2);
    cudaGetSymbolAddress((void**)&qw3, g_qw3);
    cudaGetSymbolAddress((void**)&qw4, g_qw4);
    cudaGetSymbolAddress((void**)&qwc, g_qwc);
    cudaGetSymbolAddress((void**)&wsc, g_wscale);

    // NOTE: bufA doubles as padded16 (conv1 out) — both fit (35MB < 66MB).

    // 1. halo zero (both padded buffers)
    halo_kernel<<<(2 * 32 * 4124 + 255) / 256, 256>>>(bufA, bufB);

    // 2. fused weight quant
    wquant_all<<<5, 256>>>(w1, w2, w3, w4, wc, qw1, qw2, qw3, qw4, qwc, wsc);

    // 3. input quant
    inquant_kernel<<<(32 * 256 * 256 / 4 + 255) / 256, 256>>>(x, (int*)in0, sc);

    // 4. conv1: 1->16 valid -> bufA padded16
    conv1_kernel<<<(32 * 254 * 254 + 255) / 256, 256>>>(in0, qw1, b1, bufA, sc, wsc + 0);

    // 5. conv2: 16->32 3x3 same: bufA padded16 -> bufB padded32
    conv_mma_kernel<16, 32, 3, 1><<<dim3(2, 254, 32), 128>>>(
        bufA + (size_t)ORG * 16, (long)HSP * WSP, WSP, qw2, b2,
        bufB + (size_t)ORG * 32, (long)HSP * WSP, WSP, 254, sc, wsc + 1, 2, 3, 4);

    // 6. conv3: 32->32 5x5 same: bufB padded32 -> bufA compact32   [profiled launch]
    conv_mma_kernel<32, 32, 5, 2><<<dim3(2, 254, 32), 128>>>(
        bufB + (size_t)ORG * 32, (long)HSP * WSP, WSP, qw3, b3,
        bufA, (long)254 * 254, 254, 254, sc, wsc + 2, 4, 5, 6);

    // 7. maxpool: bufA compact32 -> bufB pool-padded (stride 132)
    pool_kernel<<<(32 * 127 * 127 * 2 + 255) / 256, 256>>>(bufA, bufB, sc);

    // 8. conv4: 32->16 3x3 valid: bufB pool (RS=132) -> bufA compact16
    conv_mma_kernel<32, 16, 3, 0><<<dim3(1, 125, 32), 128>>>(
        bufB, (long)127 * 132, 132, qw4, b4,
        bufA, (long)125 * 125, 125, 125, sc, wsc + 3, 7, 8, 9);

    // 9. global avg pool + fq(s10)
    gap_kernel<<<32, 256>>>(bufA, sc);

    // 10. classifier
    fc_kernel<<<1, 512>>>(bc, out);
}

// round 7
// speedup vs baseline: 6.9981x; 1.0012x over previous
#include <cuda_runtime.h>
#include <cstdint>

#define DI __device__ __forceinline__

// exact fake-quant (used only in low-volume paths)
DI float fq_q(float x, float s) {
    float q = rintf(__fdiv_rn(x, s));
    return fminf(fmaxf(q, -128.0f), 127.0f);
}
DI float fq(float x, float s) { return fq_q(x, s) * s; }
DI int sbyte(int w, int k) { return (int)((signed char)(w >> (8 * k))); }

// ---------------- padded layout constants ----------------
// padded act buffers: 260 rows x 264 cols, logical (0,0) at (+3,+3)
#define WSP 264
#define HSP 260
#define ORG (3 * 264 + 3)

// ---------------- device global scratch ----------------
__device__ __align__(16) signed char g_bufA[(size_t)32 * 254 * 254 * 32];  // 66 MB
__device__ __align__(16) signed char g_bufB[(size_t)32 * HSP * WSP * 32];  // 70 MB
__device__ __align__(16) signed char g_in0[(size_t)32 * 256 * 256];
__device__ __align__(16) int         g_qw1[9 * 16];        // [tap][oc]
__device__ __align__(16) signed char g_qw2[9 * 32 * 16];   // [tap][oc][ic]
__device__ __align__(16) signed char g_qw3[25 * 32 * 32];
__device__ __align__(16) signed char g_qw4[9 * 16 * 32];
__device__ float g_qwc[16 * 10];
__device__ float g_wscale[8];
__device__ float g_feat[32 * 16];

// ---------------- IMMA wrappers ----------------
DI void mma_k32(int d[4], unsigned a0, unsigned a1, unsigned a2, unsigned a3,
                unsigned b0, unsigned b1) {
    asm volatile(
        "mma.sync.aligned.m16n8k32.row.col.s32.s8.s8.s32 "
        "{%0,%1,%2,%3}, {%4,%5,%6,%7}, {%8,%9}, {%0,%1,%2,%3};\n"
        : "+r"(d[0]), "+r"(d[1]), "+r"(d[2]), "+r"(d[3])
        : "r"(a0), "r"(a1), "r"(a2), "r"(a3), "r"(b0), "r"(b1));
}
DI void mma_k16(int d[4], unsigned a0, unsigned a1, unsigned b0) {
    asm volatile(
        "mma.sync.aligned.m16n8k16.row.col.s32.s8.s8.s32 "
        "{%0,%1,%2,%3}, {%4,%5}, {%6}, {%0,%1,%2,%3};\n"
        : "+r"(d[0]), "+r"(d[1]), "+r"(d[2]), "+r"(d[3])
        : "r"(a0), "r"(a1), "r"(b0));
}

// ---------------- halo zero: rings of padded buffers ----------------
// per batch: 4124 halo px (rows 0-2,257-259 full width; cols 0-2,257-263 of mid rows)
__global__ void halo_kernel(signed char* bufA16, signed char* bufB32) {
    const int ITEMS = 32 * 4124;
    int idx = blockIdx.x * 256 + threadIdx.x;
    int which = 0;
    if (idx >= ITEMS) { idx -= ITEMS; which = 1; }
    if (idx >= ITEMS) return;
    int b = idx / 4124, i = idx % 4124;
    int prow, pcol;
    if (i < 1584) {
        int pr = i / 264;
        pcol = i % 264;
        prow = (pr < 3) ? pr : 257 + (pr - 3);
    } else {
        int j = i - 1584;
        prow = 3 + j / 10;
        int pc = j % 10;
        pcol = (pc < 3) ? pc : 257 + (pc - 3);
    }
    size_t px = ((size_t)b * HSP + prow) * WSP + pcol;
    uint4 z = make_uint4(0, 0, 0, 0);
    if (which == 0) {
        *(uint4*)(bufA16 + px * 16) = z;
    } else {
        *(uint4*)(bufB32 + px * 32) = z;
        *(uint4*)(bufB32 + px * 32 + 16) = z;
    }
}

// ---------------- fused weight quant: 5 blocks ----------------
DI float blockmax_abs(const float* w, int n, float* red) {
    float m = 0.0f;
    for (int i = threadIdx.x; i < n; i += 256) m = fmaxf(m, fabsf(w[i]));
    red[threadIdx.x] = m;
    __syncthreads();
    for (int s = 128; s > 0; s >>= 1) {
        if (threadIdx.x < s) red[threadIdx.x] = fmaxf(red[threadIdx.x], red[threadIdx.x + s]);
        __syncthreads();
    }
    return red[0];
}

__global__ void wquant_all(const float* __restrict__ w1, const float* __restrict__ w2,
                           const float* __restrict__ w3, const float* __restrict__ w4,
                           const float* __restrict__ wc,
                           int* qw1, signed char* qw2, signed char* qw3, signed char* qw4,
                           float* qwc, float* wsc) {
    __shared__ float red[256];
    const int bid = blockIdx.x, tid = threadIdx.x;
    if (bid == 0) {
        float scale = __fdiv_rn(blockmax_abs(w1, 144, red), 127.0f);
        if (tid == 0) wsc[0] = scale;
        for (int i = tid; i < 144; i += 256) {
            int tap = i % 9, oc = i / 9;
            qw1[tap * 16 + oc] = (int)fq_q(w1[i], scale);
        }
    } else if (bid == 1) {
        float scale = __fdiv_rn(blockmax_abs(w2, 4608, red), 127.0f);
        if (tid == 0) wsc[1] = scale;
        for (int i = tid; i < 4608; i += 256) {
            int ic = i % 16, oc = (i / 16) % 32, tap = i / (16 * 32);
            int ky = tap / 3, kx = tap % 3;
            qw2[i] = (signed char)(int)fq_q(w2[((oc * 16 + ic) * 3 + ky) * 3 + kx], scale);
        }
    } else if (bid == 2) {
        float scale = __fdiv_rn(blockmax_abs(w3, 25600, red), 127.0f);
        if (tid == 0) wsc[2] = scale;
        for (int i = tid; i < 25600; i += 256) {
            int ic = i % 32, oc = (i / 32) % 32, tap = i / (32 * 32);
            int ky = tap / 5, kx = tap % 5;
            qw3[i] = (signed char)(int)fq_q(w3[((oc * 32 + ic) * 5 + ky) * 5 + kx], scale);
        }
    } else if (bid == 3) {
        float scale = __fdiv_rn(blockmax_abs(w4, 4608, red), 127.0f);
        if (tid == 0) wsc[3] = scale;
        for (int i = tid; i < 4608; i += 256) {
            int ic = i % 32, oc = (i / 32) % 16, tap = i / (32 * 16);
            int ky = tap / 3, kx = tap % 3;
            qw4[i] = (signed char)(int)fq_q(w4[((oc * 32 + ic) * 3 + ky) * 3 + kx], scale);
        }
    } else {
        float scale = __fdiv_rn(blockmax_abs(wc, 160, red), 127.0f);
        for (int i = tid; i < 160; i += 256) {
            int ic = i % 16, oc = i / 16;
            qwc[ic * 10 + oc] = fq_q(wc[i], scale) * scale;
        }
    }
}

// ---------------- input quant: fp32 -> packed int8 codes ----------------
__global__ void inquant_kernel(const float* __restrict__ x, int* __restrict__ out,
                               const float* __restrict__ scales) {
    int i = blockIdx.x * 256 + threadIdx.x;
    if (i >= 32 * 256 * 256 / 4) return;
    float4 v = ((const float4*)x)[i];
    float inv = __frcp_rn(scales[0]);    // 1/s0, correctly rounded reciprocal
    int c0 = max(min(__float2int_rn(v.x * inv), 127), -128);
    int c1 = max(min(__float2int_rn(v.y * inv), 127), -128);
    int c2 = max(min(__float2int_rn(v.z * inv), 127), -128);
    int c3 = max(min(__float2int_rn(v.w * inv), 127), -128);
    out[i] = (c0 & 0xFF) | ((c1 & 0xFF) << 8) | ((c2 & 0xFF) << 16) | ((c3 & 0xFF) << 24);
}

// ---------------- conv1: 1->16 3x3 valid, scalar IMAD, padded16 out ----------------
__global__ void __launch_bounds__(256) conv1_kernel(
    const signed char* __restrict__ in, const int* __restrict__ wq,
    const float* __restrict__ bias, signed char* __restrict__ out,
    const float* __restrict__ scales, const float* __restrict__ wscale) {
    __shared__ int wsm[144];
    __shared__ signed char lut[128];
    __shared__ float bsm[16];
    const int tid = threadIdx.x;
    const float sa = scales[1], sb = scales[2];
    if (tid < 128) lut[tid] = (signed char)(int)fq_q((float)tid * sa, sb);
    if (tid < 144) wsm[tid] = wq[tid];
    if (tid >= 144 && tid < 160) bsm[tid - 144] = bias[tid - 144];
    __syncthreads();

    int idx = blockIdx.x * 256 + tid;
    if (idx >= 32 * 254 * 254) return;
    int x = idx % 254, y = (idx / 254) % 254, b = idx / (254 * 254);

    const signed char* base = in + (size_t)b * 256 * 256;
    int v[9];
#pragma unroll
    for (int ky = 0; ky < 3; ky++)
#pragma unroll
        for (int kx = 0; kx < 3; kx++)
            v[ky * 3 + kx] = (int)base[(size_t)(y + ky) * 256 + (x + kx)];

    int acc[16];
#pragma unroll
    for (int j = 0; j < 16; j++) acc[j] = 0;
#pragma unroll
    for (int tap = 0; tap < 9; tap++)
#pragma unroll
        for (int j = 0; j < 16; j++) acc[j] += v[tap] * wsm[tap * 16 + j];

    const float csa = __fdiv_rn(scales[0] * wscale[0], sa);
    unsigned wds[4];
#pragma unroll
    for (int g = 0; g < 4; g++) {
        unsigned wd = 0;
#pragma unroll
        for (int k = 0; k < 4; k++) {
            int j = g * 4 + k;
            float bva = __fdiv_rn(bsm[j], sa);
            int c1 = __float2int_rn(fmaf((float)acc[j], csa, bva));
            c1 = max(min(c1, 127), 0);
            wd |= ((unsigned)(unsigned char)lut[c1]) << (8 * k);
        }
        wds[g] = wd;
    }
    size_t px = ((size_t)b * HSP + (y + 3)) * WSP + (x + 3);
    *(uint4*)(out + px * 16) = make_uint4(wds[0], wds[1], wds[2], wds[3]);
}

// ---------------- lean IMMA conv ----------------
// 4 warps/CTA; warp w owns px [w*32, w*32+32) x all OC. Unconditional LDG (padded in).
template <int ICB, int OC, int K, int PAD>
__global__ void __launch_bounds__(128) conv_mma_kernel(
    const signed char* __restrict__ in, long BSi, int RSi,
    const signed char* __restrict__ wq, const float* __restrict__ bias,
    signed char* __restrict__ out, long BSo, int RSo, int Wout,
    const float* __restrict__ scales, const float* __restrict__ wscale,
    int s_in, int s_a, int s_b) {
    constexpr int NTL = OC / 8;            // n-tiles per warp
    constexpr int NWB = K * K * OC * ICB;  // weight bytes

    __shared__ int wsm[NWB / 4];
    __shared__ signed char lut[128];
    __shared__ signed char stg[128 * OC];

    const int tid = threadIdx.x;
    const int w = tid >> 5, lane = tid & 31;
    const int g = lane >> 2, t = lane & 3;

    const float sa = scales[s_a], sb = scales[s_b];
    if (tid < 128) lut[tid] = (signed char)(int)fq_q((float)tid * sa, sb);
    for (int i = tid; i < NWB / 4; i += 128) wsm[i] = ((const int*)wq)[i];
    __syncthreads();

    const int bx = blockIdx.x, y = blockIdx.y, b = blockIdx.z;
    const int xw = bx * 128 + w * 32;
    const signed char* wsb = (const signed char*)wsm;

    int acc[2][NTL][4];
#pragma unroll
    for (int m = 0; m < 2; m++)
#pragma unroll
        for (int nt = 0; nt < NTL; nt++)
#pragma unroll
            for (int k = 0; k < 4; k++) acc[m][nt][k] = 0;

#pragma unroll
    for (int ky = 0; ky < K; ky++) {
        const signed char* rp =
            in + ((long)b * BSi + (long)(y + ky - PAD) * RSi + (xw - PAD)) * ICB;
#pragma unroll
        for (int kx = 0; kx < K; kx++) {
            const int tap = ky * K + kx;
            if constexpr (ICB == 32) {
                uint2 A[2][2];
#pragma unroll
                for (int m = 0; m < 2; m++) {
                    const signed char* p = rp + kx * 32 + (m * 16 + g) * 32 + 8 * t;
                    A[m][0] = *(const uint2*)p;
                    A[m][1] = *(const uint2*)(p + 8 * 32);
                }
#pragma unroll
                for (int nt = 0; nt < NTL; nt++) {
                    uint2 B = *(const uint2*)(wsb + ((tap * OC) + nt * 8 + g) * 32 + 8 * t);
#pragma unroll
                    for (int m = 0; m < 2; m++)
                        mma_k32(acc[m][nt], A[m][0].x, A[m][1].x, A[m][0].y, A[m][1].y,
                                B.x, B.y);
                }
            } else {  // ICB == 16, k16 MMA
                unsigned A[2][2];
#pragma unroll
                for (int m = 0; m < 2; m++) {
                    const signed char* p = rp + kx * 16 + (m * 16 + g) * 16 + 4 * t;
                    A[m][0] = *(const unsigned*)p;
                    A[m][1] = *(const unsigned*)(p + 8 * 16);
                }
#pragma unroll
                for (int nt = 0; nt < NTL; nt++) {
                    unsigned B = *(const unsigned*)(wsb + ((tap * OC) + nt * 8 + g) * 16 + 4 * t);
#pragma unroll
                    for (int m = 0; m < 2; m++) mma_k16(acc[m][nt], A[m][0], A[m][1], B);
                }
            }
        }
    }

    // epilogue: c1 = clamp(rni(acc*cs' + b'), 0, 127); byte = lut[c1]
    const float csa = __fdiv_rn(scales[s_in] * wscale[0], sa);
    float bva[NTL][2];
#pragma unroll
    for (int nt = 0; nt < NTL; nt++) {
        bva[nt][0] = __fdiv_rn(bias[nt * 8 + 2 * t], sa);
        bva[nt][1] = __fdiv_rn(bias[nt * 8 + 2 * t + 1], sa);
    }
#pragma unroll
    for (int m = 0; m < 2; m++)
#pragma unroll
        for (int r = 0; r < 2; r++) {
            const int px = w * 32 + m * 16 + r * 8 + g;
#pragma unroll
            for (int nt = 0; nt < NTL; nt++) {
                int c0 = __float2int_rn(fmaf((float)acc[m][nt][2 * r + 0], csa, bva[nt][0]));
                int c1 = __float2int_rn(fmaf((float)acc[m][nt][2 * r + 1], csa, bva[nt][1]));
                c0 = max(min(c0, 127), 0);
                c1 = max(min(c1, 127), 0);
                unsigned short pk = (unsigned short)((unsigned char)lut[c0] |
                                    ((unsigned)(unsigned char)lut[c1] << 8));
                *(unsigned short*)(stg + px * OC + nt * 8 + 2 * t) = pk;
            }
        }
    __syncthreads();

    // cooperative vector store
#pragma unroll
    for (int i = tid; i < 128 * OC / 16; i += 128) {
        const int px = (16 * i) / OC;
        if (bx * 128 + px < Wout) {
            signed char* dst = out + ((long)b * BSo + (long)y * RSo + bx * 128) * OC + 16 * i;
            *(uint4*)dst = *(const uint4*)(stg + 16 * i);
        }
    }
}

// ---------------- maxpool 2x2 + LUT requant: compact32 in -> pool-padded out ----------------
__global__ void pool_kernel(const signed char* __restrict__ in, signed char* __restrict__ out,
                            const float* __restrict__ scales) {
    __shared__ signed char lut[128];
    const int tid = threadIdx.x;
    const float s6 = scales[6], s7 = scales[7];
    if (tid < 128) lut[tid] = (signed char)(int)fq_q((float)tid * s6, s7);
    __syncthreads();

    int idx = blockIdx.x * 256 + tid;
    const int total = 32 * 127 * 127 * 2;
    if (idx >= total) return;
    int half = idx & 1;
    int p = idx >> 1;
    int x = p % 127, y = (p / 127) % 127, b = p / (127 * 127);

    const signed char* src = in + (((size_t)(b * 254 + 2 * y)) * 254 + 2 * x) * 32 + half * 16;
    int4 v00 = *(const int4*)src;
    int4 v01 = *(const int4*)(src + 32);
    int4 v10 = *(const int4*)(src + 254 * 32);
    int4 v11 = *(const int4*)(src + 254 * 32 + 32);
    int mw[4];
    mw[0] = __vmaxs4(__vmaxs4(v00.x, v01.x), __vmaxs4(v10.x, v11.x));
    mw[1] = __vmaxs4(__vmaxs4(v00.y, v01.y), __vmaxs4(v10.y, v11.y));
    mw[2] = __vmaxs4(__vmaxs4(v00.z, v01.z), __vmaxs4(v10.z, v11.z));
    mw[3] = __vmaxs4(__vmaxs4(v00.w, v01.w), __vmaxs4(v10.w, v11.w));

    unsigned rw[4];
#pragma unroll
    for (int ww = 0; ww < 4; ww++) {
        unsigned r = 0;
#pragma unroll
        for (int k = 0; k < 4; k++)
            r |= ((unsigned)(unsigned char)lut[sbyte(mw[ww], k)]) << (8 * k);
        rw[ww] = r;
    }
    *(uint4*)(out + (((size_t)(b * 127 + y)) * 132 + x) * 32 + half * 16) =
        make_uint4(rw[0], rw[1], rw[2], rw[3]);
}

// ---------------- global avg pool (compact16 in) + fq(s10) ----------------
__global__ void gap_kernel(const signed char* __restrict__ in, const float* __restrict__ scales) {
    __shared__ int red[256][16];
    const int b = blockIdx.x, tid = threadIdx.x;
    int acc[16];
#pragma unroll
    for (int k = 0; k < 16; k++) acc[k] = 0;
    const signed char* p = in + (size_t)b * 125 * 125 * 16;
    for (int i = tid; i < 125 * 125; i += 256) {
        int4 v = *(const int4*)(p + (size_t)i * 16);
        int wv[4] = {v.x, v.y, v.z, v.w};
#pragma unroll
        for (int j = 0; j < 4; j++)
#pragma unroll
            for (int k = 0; k < 4; k++) acc[j * 4 + k] += sbyte(wv[j], k);
    }
#pragma unroll
    for (int k = 0; k < 16; k++) red[tid][k] = acc[k];
    __syncthreads();
    for (int s = 128; s > 0; s >>= 1) {
        if (tid < s)
#pragma unroll
            for (int k = 0; k < 16; k++) red[tid][k] += red[tid + s][k];
        __syncthreads();
    }
    if (tid < 16) {
        float mean = __fdiv_rn((float)red[0][tid] * scales[9], 15625.0f);
        g_feat[b * 16 + tid] = fq(mean, scales[10]);
    }
}

// ---------------- classifier ----------------
__global__ void fc_kernel(const float* __restrict__ bias, float* __restrict__ out) {
    int tt = threadIdx.x;
    if (tt >= 320) return;
    int b = tt / 10, j = tt % 10;
    float s = bias[j];
#pragma unroll
    for (int k = 0; k < 16; k++) s += g_feat[b * 16 + k] * g_qwc[k * 10 + j];
    out[b * 10 + j] = s;
}

// ---------------- launcher ----------------
extern "C" void kernel_launch(void* const* d_in, const int* in_sizes, int n_in,
                              void* d_out, int out_size) {
    const float* x  = (const float*)d_in[0];
    const float* w1 = (const float*)d_in[1];
    const float* b1 = (const float*)d_in[2];
    const float* w2 = (const float*)d_in[3];
    const float* b2 = (const float*)d_in[4];
    const float* w3 = (const float*)d_in[5];
    const float* b3 = (const float*)d_in[6];
    const float* w4 = (const float*)d_in[7];
    const float* b4 = (const float*)d_in[8];
    const float* wc = (const float*)d_in[9];
    const float* bc = (const float*)d_in[10];
    const float* sc = (const float*)d_in[11];
    float* out = (float*)d_out;

    signed char *bufA, *bufB, *in0, *qw2, *qw3, *qw4;
    int* qw1;
    float *qwc, *wsc;
    cudaGetSymbolAddress((void**)&bufA, g_bufA);
    cudaGetSymbolAddress((void**)&bufB, g_bufB);
    cudaGetSymbolAddress((void**)&in0, g_in0);
    cudaGetSymbolAddress((void**)&qw1, g_qw1);
    cudaGetSymbolAddress((void**)&qw2, g_qw2);
    cudaGetSymbolAddress((void**)&qw3, g_qw3);
    cudaGetSymbolAddress((void**)&qw4, g_qw4);
    cudaGetSymbolAddress((void**)&qwc, g_qwc);
    cudaGetSymbolAddress((void**)&wsc, g_wscale);

    // NOTE: bufA doubles as padded16 (conv1 out) — both fit (35MB < 66MB).

    // 1. halo zero (both padded buffers)
    halo_kernel<<<(2 * 32 * 4124 + 255) / 256, 256>>>(bufA, bufB);

    // 2. fused weight quant
    wquant_all<<<5, 256>>>(w1, w2, w3, w4, wc, qw1, qw2, qw3, qw4, qwc, wsc);

    // 3. input quant
    inquant_kernel<<<(32 * 256 * 256 / 4 + 255) / 256, 256>>>(x, (int*)in0, sc);

    // 4. conv1: 1->16 valid -> bufA padded16
    conv1_kernel<<<(32 * 254 * 254 + 255) / 256, 256>>>(in0, qw1, b1, bufA, sc, wsc + 0);

    // 5. conv2: 16->32 3x3 same: bufA padded16 -> bufB padded32
    conv_mma_kernel<16, 32, 3, 1><<<dim3(2, 254, 32), 128>>>(
        bufA + (size_t)ORG * 16, (long)HSP * WSP, WSP, qw2, b2,
        bufB + (size_t)ORG * 32, (long)HSP * WSP, WSP, 254, sc, wsc + 1, 2, 3, 4);

    // 6. conv3: 32->32 5x5 same: bufB padded32 -> bufA compact32   [profiled launch]
    conv_mma_kernel<32, 32, 5, 2><<<dim3(2, 254, 32), 128>>>(
        bufB + (size_t)ORG * 32, (long)HSP * WSP, WSP, qw3, b3,
        bufA, (long)254 * 254, 254, 254, sc, wsc + 2, 4, 5, 6);

    // 7. maxpool: bufA compact32 -> bufB pool-padded (stride 132)
    pool_kernel<<<(32 * 127 * 127 * 2 + 255) / 256, 256>>>(bufA, bufB, sc);

    // 8. conv4: 32->16 3x3 valid: bufB pool (RS=132) -> bufA compact16
    conv_mma_kernel<32, 16, 3, 0><<<dim3(1, 125, 32), 128>>>(
        bufB, (long)127 * 132, 132, qw4, b4,
        bufA, (long)125 * 125, 125, 125, sc, wsc + 3, 7, 8, 9);

    // 9. global avg pool + fq(s10)
    gap_kernel<<<32, 256>>>(bufA, sc);

    // 10. classifier
    fc_kernel<<<1, 512>>>(bc, out);
}

// round 9
// speedup vs baseline: 7.1279x; 1.0185x over previous
#include <cuda_runtime.h>
#include <cstdint>

#define DI __device__ __forceinline__

DI float fq_q(float x, float s) {
    float q = rintf(__fdiv_rn(x, s));
    return fminf(fmaxf(q, -128.0f), 127.0f);
}
DI float fq(float x, float s) { return fq_q(x, s) * s; }
DI int sbyte(int w, int k) { return (int)((signed char)(w >> (8 * k))); }

#define WSP 264
#define HSP 260
#define ORG (3 * 264 + 3)

// ---------------- scratch ----------------
__device__ __align__(16) signed char g_pad16[(size_t)32 * HSP * WSP * 16];  // conv1 out
__device__ __align__(16) signed char g_pad32[(size_t)32 * HSP * WSP * 32];  // conv2 out
__device__ __align__(16) signed char g_c3[(size_t)32 * 254 * 254 * 32];     // conv3 out
__device__ __align__(16) signed char g_pool[(size_t)32 * 127 * 132 * 32];   // pool out
__device__ __align__(16) signed char g_c4[(size_t)32 * 125 * 125 * 16];     // conv4 out
__device__ __align__(16) signed char g_in0[(size_t)32 * 256 * 256];
__device__ __align__(16) int g_qw1[9 * 16];
__device__ __align__(16) signed char g_qw2[6 * 32 * 32];    // paired [st][oc][j]
__device__ __align__(16) signed char g_qw3[25 * 32 * 32];   // [tap][oc][ic]
__device__ __align__(16) signed char g_qw4[9 * 16 * 32];    // [tap][oc][ic]
__device__ float g_qwc[160], g_wscale[8], g_feat[512];

// ---------------- IMMA k32 ----------------
DI void mma_k32(int d[4], unsigned a0, unsigned a1, unsigned a2, unsigned a3,
                unsigned b0, unsigned b1) {
    asm volatile(
        "mma.sync.aligned.m16n8k32.row.col.s32.s8.s8.s32 "
        "{%0,%1,%2,%3}, {%4,%5,%6,%7}, {%8,%9}, {%0,%1,%2,%3};\n"
        : "+r"(d[0]), "+r"(d[1]), "+r"(d[2]), "+r"(d[3])
        : "r"(a0), "r"(a1), "r"(a2), "r"(a3), "r"(b0), "r"(b1));
}

// ---------------- fused prep: inquant + weight quant + halo zero ----------------
DI float bmax(const float* w, int n, float* red) {
    float m = 0.0f;
    for (int i = threadIdx.x; i < n; i += 256) m = fmaxf(m, fabsf(w[i]));
    red[threadIdx.x] = m;
    __syncthreads();
    for (int s = 128; s > 0; s >>= 1) {
        if (threadIdx.x < s) red[threadIdx.x] = fmaxf(red[threadIdx.x], red[threadIdx.x + s]);
        __syncthreads();
    }
    return red[0];
}

__global__ void prep_kernel(const float* __restrict__ x, const float* __restrict__ w1,
                            const float* __restrict__ w2, const float* __restrict__ w3,
                            const float* __restrict__ w4, const float* __restrict__ wc,
                            const float* __restrict__ sc) {
    __shared__ float red[256];
    const int blk = blockIdx.x, tid = threadIdx.x;
    if (blk < 2048) {  // input quant
        int i = blk * 256 + tid;
        float4 v = ((const float4*)x)[i];
        float inv = __frcp_rn(sc[0]);
        int c0 = max(min(__float2int_rn(v.x * inv), 127), -128);
        int c1 = max(min(__float2int_rn(v.y * inv), 127), -128);
        int c2 = max(min(__float2int_rn(v.z * inv), 127), -128);
        int c3 = max(min(__float2int_rn(v.w * inv), 127), -128);
        ((int*)g_in0)[i] = (c0 & 0xFF) | ((c1 & 0xFF) << 8) | ((c2 & 0xFF) << 16) |
                           ((c3 & 0xFF) << 24);
    } else if (blk == 2048) {
        float s = __fdiv_rn(bmax(w1, 144, red), 127.0f);
        if (tid == 0) g_wscale[0] = s;
        for (int i = tid; i < 144; i += 256) g_qw1[(i % 9) * 16 + i / 9] = (int)fq_q(w1[i], s);
    } else if (blk == 2049) {  // conv2 paired image [st][oc][j]
        float s = __fdiv_rn(bmax(w2, 4608, red), 127.0f);
        if (tid == 0) g_wscale[1] = s;
        for (int i = tid; i < 6144; i += 256) {
            int j = i & 31, oc = (i >> 5) & 31, st = i >> 10;
            int ky = st >> 1, p = st & 1;
            int kx = 2 * p + (j >= 16), ic = j & 15;
            signed char v = 0;
            if (kx < 3) v = (signed char)(int)fq_q(w2[((oc * 16 + ic) * 3 + ky) * 3 + kx], s);
            g_qw2[i] = v;
        }
    } else if (blk == 2050) {  // conv3 [tap][oc][ic]
        float s = __fdiv_rn(bmax(w3, 25600, red), 127.0f);
        if (tid == 0) g_wscale[2] = s;
        for (int i = tid; i < 25600; i += 256) {
            int ic = i & 31, oc = (i >> 5) & 31, tap = i >> 10;
            g_qw3[i] = (signed char)(int)fq_q(w3[((oc * 32 + ic) * 5 + tap / 5) * 5 + tap % 5], s);
        }
    } else if (blk == 2051) {  // conv4 [tap][oc][ic]
        float s = __fdiv_rn(bmax(w4, 4608, red), 127.0f);
        if (tid == 0) g_wscale[3] = s;
        for (int i = tid; i < 4608; i += 256) {
            int ic = i & 31, oc = (i >> 5) & 15, tap = i >> 9;
            g_qw4[i] = (signed char)(int)fq_q(w4[((oc * 32 + ic) * 3 + tap / 3) * 3 + tap % 3], s);
        }
    } else if (blk == 2052) {
        float s = __fdiv_rn(bmax(wc, 160, red), 127.0f);
        for (int i = tid; i < 160; i += 256) g_qwc[(i % 16) * 10 + i / 16] = fq_q(wc[i], s) * s;
    } else {  // halo zero for pad16 / pad32
        int idx = (blk - 2053) * 256 + tid;
        const int ITEMS = 32 * 4124;
        int which = idx >= ITEMS;
        if (which) idx -= ITEMS;
        int b = idx / 4124, i = idx % 4124, pr, pc;
        if (i < 1584) { pc = i % 264; int r = i / 264; pr = (r < 3) ? r : 254 + r; }
        else { int j = i - 1584; pr = 3 + j / 10; int c = j % 10; pc = (c < 3) ? c : 254 + c; }
        size_t px = ((size_t)b * HSP + pr) * WSP + pc;
        uint4 z = make_uint4(0, 0, 0, 0);
        if (!which) {
            *(uint4*)(g_pad16 + px * 16) = z;
        } else {
            uint4* d = (uint4*)(g_pad32 + px * 32);
            d[0] = z; d[1] = z;
        }
    }
}

// ---------------- conv1: 1->16 3x3 valid scalar IMAD ----------------
__global__ void __launch_bounds__(256) conv1_kernel(const float* __restrict__ bias,
                                                    const float* __restrict__ sc) {
    __shared__ int wsm[144];
    __shared__ signed char lut[128];
    __shared__ float bsm[16];
    const int tid = threadIdx.x;
    const float sa = sc[1], sb = sc[2];
    if (tid < 128) lut[tid] = (signed char)(int)fq_q((float)tid * sa, sb);
    if (tid < 144) wsm[tid] = g_qw1[tid];
    if (tid >= 144 && tid < 160) bsm[tid - 144] = bias[tid - 144];
    __syncthreads();
    int idx = blockIdx.x * 256 + tid;
    if (idx >= 32 * 254 * 254) return;
    int x = idx % 254, y = (idx / 254) % 254, b = idx / (254 * 254);
    const signed char* base = g_in0 + (size_t)b * 65536;
    int v[9];
#pragma unroll
    for (int ky = 0; ky < 3; ky++)
#pragma unroll
        for (int kx = 0; kx < 3; kx++)
            v[ky * 3 + kx] = (int)base[(size_t)(y + ky) * 256 + x + kx];
    int acc[16];
#pragma unroll
    for (int j = 0; j < 16; j++) acc[j] = 0;
#pragma unroll
    for (int t = 0; t < 9; t++)
#pragma unroll
        for (int j = 0; j < 16; j++) acc[j] += v[t] * wsm[t * 16 + j];
    const float csa = __fdiv_rn(sc[0] * g_wscale[0], sa);
    unsigned wds[4];
#pragma unroll
    for (int g = 0; g < 4; g++) {
        unsigned wd = 0;
#pragma unroll
        for (int k = 0; k < 4; k++) {
            int j = g * 4 + k;
            int c = __float2int_rn(fmaf((float)acc[j], csa, __fdiv_rn(bsm[j], sa)));
            wd |= ((unsigned)(unsigned char)lut[max(min(c, 127), 0)]) << (8 * k);
        }
        wds[g] = wd;
    }
    *(uint4*)(g_pad16 + (((size_t)b * HSP + y + 3) * WSP + x + 3) * 16) =
        make_uint4(wds[0], wds[1], wds[2], wds[3]);
}

// ---------------- IMMA conv, Y-loop amortized ----------------
// PXB: bytes per pixel; K: ky taps; KXS: k32 steps per ky; KXW: px advance per step; YB rows/CTA
template <int PXB, int OC, int K, int KXS, int KXW, int YB>
__global__ void __launch_bounds__(128) conv_mma_kernel(
    const signed char* __restrict__ in, long BSi, int RSi, int PAD,
    const signed char* __restrict__ wq, const float* __restrict__ bias,
    signed char* __restrict__ out, long BSo, int RSo, int Wout, int Hout,
    const float* __restrict__ sc, const float* __restrict__ wsc,
    int s_in, int s_a, int s_b) {
    constexpr int NTL = OC / 8;
    constexpr int NWB = K * KXS * OC * 32;

    __shared__ int wsm[NWB / 4];
    __shared__ signed char lut[128];
    __shared__ __align__(16) signed char stg[4][32 * OC];

    const int tid = threadIdx.x;
    const int w = tid >> 5, lane = tid & 31;
    const int g = lane >> 2, t = lane & 3;

    const float sa = sc[s_a];
    if (tid < 128) lut[tid] = (signed char)(int)fq_q((float)tid * sa, sc[s_b]);
    for (int i = tid; i < NWB / 4; i += 128) wsm[i] = ((const int*)wq)[i];
    __syncthreads();

    const int bx = blockIdx.x, b = blockIdx.z;
    const int xw = bx * 128 + w * 32;
    const signed char* wsb = (const signed char*)wsm;

    const float csa = __fdiv_rn(sc[s_in] * wsc[0], sa);
    float bva[NTL][2];
#pragma unroll
    for (int nt = 0; nt < NTL; nt++) {
        bva[nt][0] = __fdiv_rn(bias[nt * 8 + 2 * t], sa);
        bva[nt][1] = __fdiv_rn(bias[nt * 8 + 2 * t + 1], sa);
    }

#pragma unroll 1
    for (int yi = 0; yi < YB; yi++) {
        const int y = blockIdx.y * YB + yi;
        if (y >= Hout) break;

        int acc[2][NTL][4];
#pragma unroll
        for (int m = 0; m < 2; m++)
#pragma unroll
            for (int nt = 0; nt < NTL; nt++)
#pragma unroll
                for (int k = 0; k < 4; k++) acc[m][nt][k] = 0;

#pragma unroll
        for (int ky = 0; ky < K; ky++) {
            const signed char* rp =
                in + ((long)b * BSi + (long)(y + ky - PAD) * RSi + (xw - PAD)) * PXB;
#pragma unroll
            for (int s = 0; s < KXS; s++) {
                uint2 A[2][2];
#pragma unroll
                for (int m = 0; m < 2; m++) {
                    const signed char* p = rp + (m * 16 + g) * PXB + s * KXW * PXB + 8 * t;
                    A[m][0] = *(const uint2*)p;
                    A[m][1] = *(const uint2*)(p + 8 * PXB);
                }
#pragma unroll
                for (int nt = 0; nt < NTL; nt++) {
                    uint2 B = *(const uint2*)(wsb + (((ky * KXS + s) * OC) + nt * 8 + g) * 32 + 8 * t);
#pragma unroll
                    for (int m = 0; m < 2; m++)
                        mma_k32(acc[m][nt], A[m][0].x, A[m][1].x, A[m][0].y, A[m][1].y,
                                B.x, B.y);
                }
            }
        }

        // epilogue -> warp-private smem slice
#pragma unroll
        for (int m = 0; m < 2; m++)
#pragma unroll
            for (int r = 0; r < 2; r++) {
                const int pxl = m * 16 + r * 8 + g;
#pragma unroll
                for (int nt = 0; nt < NTL; nt++) {
                    int c0 = __float2int_rn(fmaf((float)acc[m][nt][2 * r + 0], csa, bva[nt][0]));
                    int c1 = __float2int_rn(fmaf((float)acc[m][nt][2 * r + 1], csa, bva[nt][1]));
                    c0 = max(min(c0, 127), 0);
                    c1 = max(min(c1, 127), 0);
                    unsigned short pk = (unsigned short)((unsigned char)lut[c0] |
                                        ((unsigned)(unsigned char)lut[c1] << 8));
                    *(unsigned short*)(stg[w] + pxl * OC + nt * 8 + 2 * t) = pk;
                }
            }
        __syncwarp();

        // warp-local coalesced store (32 px x OC bytes = 2*OC uint4)
#pragma unroll
        for (int i = lane; i < 2 * OC; i += 32) {
            const int pxl = (16 * i) / OC;
            const int x = xw + pxl;
            if (x < Wout)
                *(uint4*)(out + ((long)b * BSo + (long)y * RSo + x) * OC + (16 * i) % OC) =
                    ((const uint4*)stg[w])[i];
        }
        __syncwarp();
    }
}

// ---------------- maxpool 2x2 + LUT requant (compact32 -> pool 132-stride) ----------------
__global__ void pool_kernel(const float* __restrict__ sc) {
    __shared__ signed char lut[128];
    const int tid = threadIdx.x;
    if (tid < 128) lut[tid] = (signed char)(int)fq_q((float)tid * sc[6], sc[7]);
    __syncthreads();
    int idx = blockIdx.x * 256 + tid;
    if (idx >= 32 * 127 * 127 * 2) return;
    int half = idx & 1, p = idx >> 1;
    int x = p % 127, y = (p / 127) % 127, b = p / (127 * 127);
    const signed char* src = g_c3 + (((size_t)(b * 254 + 2 * y)) * 254 + 2 * x) * 32 + half * 16;
    int4 v00 = *(const int4*)src;
    int4 v01 = *(const int4*)(src + 32);
    int4 v10 = *(const int4*)(src + 254 * 32);
    int4 v11 = *(const int4*)(src + 254 * 32 + 32);
    int mw[4];
    mw[0] = __vmaxs4(__vmaxs4(v00.x, v01.x), __vmaxs4(v10.x, v11.x));
    mw[1] = __vmaxs4(__vmaxs4(v00.y, v01.y), __vmaxs4(v10.y, v11.y));
    mw[2] = __vmaxs4(__vmaxs4(v00.z, v01.z), __vmaxs4(v10.z, v11.z));
    mw[3] = __vmaxs4(__vmaxs4(v00.w, v01.w), __vmaxs4(v10.w, v11.w));
    unsigned rw[4];
#pragma unroll
    for (int ww = 0; ww < 4; ww++) {
        unsigned r = 0;
#pragma unroll
        for (int k = 0; k < 4; k++)
            r |= ((unsigned)(unsigned char)lut[sbyte(mw[ww], k)]) << (8 * k);
        rw[ww] = r;
    }
    *(uint4*)(g_pool + (((size_t)(b * 127 + y)) * 132 + x) * 32 + half * 16) =
        make_uint4(rw[0], rw[1], rw[2], rw[3]);
}

// ---------------- global avg pool ----------------
__global__ void gap_kernel(const float* __restrict__ sc) {
    __shared__ int red[256][16];
    const int b = blockIdx.x, tid = threadIdx.x;
    int acc[16];
#pragma unroll
    for (int k = 0; k < 16; k++) acc[k] = 0;
    const signed char* p = g_c4 + (size_t)b * 125 * 125 * 16;
    for (int i = tid; i < 125 * 125; i += 256) {
        int4 v = *(const int4*)(p + (size_t)i * 16);
        int wv[4] = {v.x, v.y, v.z, v.w};
#pragma unroll
        for (int j = 0; j < 4; j++)
#pragma unroll
            for (int k = 0; k < 4; k++) acc[j * 4 + k] += sbyte(wv[j], k);
    }
#pragma unroll
    for (int k = 0; k < 16; k++) red[tid][k] = acc[k];
    __syncthreads();
    for (int s = 128; s > 0; s >>= 1) {
        if (tid < s)
#pragma unroll
            for (int k = 0; k < 16; k++) red[tid][k] += red[tid + s][k];
        __syncthreads();
    }
    if (tid < 16)
        g_feat[b * 16 + tid] = fq(__fdiv_rn((float)red[0][tid] * sc[9], 15625.0f), sc[10]);
}

__global__ void fc_kernel(const float* __restrict__ bias, float* __restrict__ out) {
    int t = threadIdx.x;
    if (t >= 320) return;
    int b = t / 10, j = t % 10;
    float s = bias[j];
#pragma unroll
    for (int k = 0; k < 16; k++) s += g_feat[b * 16 + k] * g_qwc[k * 10 + j];
    out[b * 10 + j] = s;
}

// ---------------- launcher ----------------
extern "C" void kernel_launch(void* const* d_in, const int* in_sizes, int n_in,
                              void* d_out, int out_size) {
    const float* x  = (const float*)d_in[0];
    const float* w1 = (const float*)d_in[1];
    const float* b1 = (const float*)d_in[2];
    const float* w2 = (const float*)d_in[3];
    const float* b2 = (const float*)d_in[4];
    const float* w3 = (const float*)d_in[5];
    const float* b3 = (const float*)d_in[6];
    const float* w4 = (const float*)d_in[7];
    const float* b4 = (const float*)d_in[8];
    const float* wc = (const float*)d_in[9];
    const float* bc = (const float*)d_in[10];
    const float* sc = (const float*)d_in[11];
    float* out = (float*)d_out;

    signed char *pad16, *pad32, *poolb, *qw2, *qw3, *qw4;
    float* wsc;
    cudaGetSymbolAddress((void**)&pad16, g_pad16);
    cudaGetSymbolAddress((void**)&pad32, g_pad32);
    cudaGetSymbolAddress((void**)&poolb, g_pool);
    cudaGetSymbolAddress((void**)&qw2, g_qw2);
    cudaGetSymbolAddress((void**)&qw3, g_qw3);
    cudaGetSymbolAddress((void**)&qw4, g_qw4);
    cudaGetSymbolAddress((void**)&wsc, g_wscale);
    signed char *c3, *c4;
    cudaGetSymbolAddress((void**)&c3, g_c3);
    cudaGetSymbolAddress((void**)&c4, g_c4);

    // 1. prep (inquant + weights + halo)
    prep_kernel<<<2053 + 1031, 256>>>(x, w1, w2, w3, w4, wc, sc);

    // 2. conv1: 1->16 valid -> pad16
    conv1_kernel<<<(32 * 254 * 254 + 255) / 256, 256>>>(b1, sc);

    // 3. conv2: 16->32 3x3 same (k32-paired) : pad16 -> pad32
    conv_mma_kernel<16, 32, 3, 2, 2, 8><<<dim3(2, 32, 32), 128>>>(
        pad16 + (size_t)ORG * 16, (long)HSP * WSP, WSP, 1, qw2, b2,
        pad32 + (size_t)ORG * 32, (long)HSP * WSP, WSP, 254, 254, sc, wsc + 1, 2, 3, 4);

    // 4. conv3: 32->32 5x5 same : pad32 -> c3 compact   [profiled launch]
    conv_mma_kernel<32, 32, 5, 5, 1, 8><<<dim3(2, 32, 32), 128>>>(
        pad32 + (size_t)ORG * 32, (long)HSP * WSP, WSP, 2, qw3, b3,
        c3, (long)254 * 254, 254, 254, 254, sc, wsc + 2, 4, 5, 6);

    // 5. maxpool -> pool (132-stride)
    pool_kernel<<<(32 * 127 * 127 * 2 + 255) / 256, 256>>>(sc);

    // 6. conv4: 32->16 3x3 valid : pool -> c4 compact
    conv_mma_kernel<32, 16, 3, 3, 1, 8><<<dim3(1, 16, 32), 128>>>(
        poolb, (long)127 * 132, 132, 0, qw4, b4,
        c4, (long)125 * 125, 125, 125, 125, sc, wsc + 3, 7, 8, 9);

    // 7. gap + 8. fc
    gap_kernel<<<32, 256>>>(sc);
    fc_kernel<<<1, 512>>>(bc, out);
}